// round 1
// baseline (speedup 1.0000x reference)
#include <cuda_runtime.h>
#include <math.h>

#define BS   2
#define NP   4096
#define CH   64
#define IMH  128
#define IMW  256
#define QPB  (IMH*IMW)     // 32768 queries per batch
#define TPB  256

// Scratch: feature tensor transposed to [b][point][channel] for coalesced gather.
__device__ float g_featT[BS * NP * CH];

__global__ void k_transpose(const float* __restrict__ feat) {
    int idx = blockIdx.x * blockDim.x + threadIdx.x;   // over BS*CH*NP
    if (idx >= BS * CH * NP) return;
    int b = idx / (CH * NP);
    int r = idx - b * (CH * NP);
    int c = r >> 12;          // / NP (4096)
    int i = r & (NP - 1);
    g_featT[(b * NP + i) * CH + c] = feat[idx];
}

// Shared memory layout (floats):
//   pts   : NP float4 (px, py, psq, 0)          -> 16384 floats
//   wouts : 64x64 out-conv weights              ->  4096
//   w2s   : 64x3                                 ->   192
//   b2s   : 64, bouts : 64, w1s : 9, b1s : 3
#define SMEM_FLOATS (NP*4 + CH*CH + CH*3 + CH + CH + 9 + 3)
#define SMEM_BYTES  (SMEM_FLOATS * 4)

__global__ __launch_bounds__(TPB, 2)
void k_main(const float* __restrict__ uv,
            const float* __restrict__ w1, const float* __restrict__ b1,
            const float* __restrict__ w2, const float* __restrict__ b2,
            const float* __restrict__ w_out, const float* __restrict__ b_out,
            float* __restrict__ out)
{
    extern __shared__ float sm[];
    float4* pts   = (float4*)sm;
    float*  wouts = sm + NP * 4;
    float*  w2s   = wouts + CH * CH;
    float*  b2s   = w2s + CH * 3;
    float*  bouts = b2s + CH;
    float*  w1s   = bouts + CH;
    float*  b1s   = w1s + 9;

    const int tid = threadIdx.x;
    const int b   = blockIdx.y;

    // ---- Phase 0: cooperative loads ----
    const float* uvb = uv + b * 2 * NP;
    for (int i = tid; i < NP; i += TPB) {
        float px = uvb[i];
        float py = uvb[NP + i];
        // p_sq exactly as reference: rn(px*px) + rn(py*py)
        float psq = __fadd_rn(__fmul_rn(px, px), __fmul_rn(py, py));
        pts[i] = make_float4(px, py, psq, 0.f);
    }
    for (int i = tid; i < CH * CH; i += TPB) wouts[i] = w_out[i];
    if (tid < CH * 3) w2s[tid] = w2[tid];
    if (tid < CH) { b2s[tid] = b2[tid]; bouts[tid] = b_out[tid]; }
    if (tid < 9)  w1s[tid] = w1[tid];
    if (tid < 3)  b1s[tid] = b1[tid];
    __syncthreads();

    // ---- Phase 1: brute-force top-3 KNN (reference distance formula) ----
    const int   q   = blockIdx.x * TPB + tid;
    const float gx  = (float)(q & (IMW - 1));
    const float gy  = (float)(q >> 8);
    const float qsq = gx * gx + gy * gy;   // exact for integer coords

    float d0 = INFINITY, d1 = INFINITY, d2b = INFINITY;
    int   i0 = 0, i1 = 0, i2 = 0;

    #pragma unroll 4
    for (int j = 0; j < NP; ++j) {
        float4 p  = pts[j];                                    // broadcast LDS.128
        float  cr = __fmaf_rn(p.y, gy, __fmul_rn(p.x, gx));    // dot over c: mul then fma
        float  dd = __fsub_rn(__fadd_rn(qsq, p.z), __fadd_rn(cr, cr));
        if (dd < d2b) {                       // strict < : ties keep lower index
            if (dd < d1) {
                d2b = d1; i2 = i1;
                if (dd < d0) { d1 = d0; i1 = i0; d0 = dd; i0 = j; }
                else         { d1 = dd; i1 = j; }
            } else { d2b = dd; i2 = j; }
        }
    }

    // ---- Phase 2: score MLP + feature gather ----
    float fin[CH];
    #pragma unroll
    for (int c = 0; c < CH; ++c) fin[c] = 0.f;

    int nidx[3] = { i0, i1, i2 };
    #pragma unroll
    for (int k = 0; k < 3; ++k) {
        int id = nidx[k];
        float4 p  = pts[id];
        float  dx = __fsub_rn(p.x, gx);
        float  dy = __fsub_rn(p.y, gy);
        float  nrm = __fsqrt_rn(__fadd_rn(__fmul_rn(dx, dx), __fmul_rn(dy, dy)));
        float h[3];
        #pragma unroll
        for (int j = 0; j < 3; ++j) {
            float t = __fmaf_rn(w1s[j*3+2], nrm,
                      __fmaf_rn(w1s[j*3+1], dy, __fmul_rn(w1s[j*3+0], dx)));
            t = t + b1s[j];
            h[j] = (t >= 0.f) ? t : 0.1f * t;     // leaky relu 0.1
        }
        const float4* fr = (const float4*)(g_featT + ((b * NP + id) << 6));
        #pragma unroll
        for (int c4 = 0; c4 < CH / 4; ++c4) {
            float4 f = fr[c4];
            #pragma unroll
            for (int jj = 0; jj < 4; ++jj) {
                int c = c4 * 4 + jj;
                float z = __fmaf_rn(w2s[c*3+2], h[2],
                          __fmaf_rn(w2s[c*3+1], h[1], __fmul_rn(w2s[c*3+0], h[0])));
                z = z + b2s[c];
                float s = __fdividef(1.f, 1.f + __expf(-z));   // sigmoid
                float fv = (jj == 0) ? f.x : (jj == 1) ? f.y : (jj == 2) ? f.z : f.w;
                fin[c] = __fmaf_rn(s, fv, fin[c]);
            }
        }
    }

    // ---- Phase 3: fused 64x64 out-conv + leaky, coalesced writes ----
    float* outb = out + ((size_t)b * CH) * QPB + q;
    for (int co = 0; co < CH; ++co) {
        const float4* wr = (const float4*)(wouts + co * CH);
        float a0 = 0.f, a1 = 0.f, a2 = 0.f, a3 = 0.f;   // 4-way ILP
        #pragma unroll
        for (int c4 = 0; c4 < CH / 4; ++c4) {
            float4 w = wr[c4];
            a0 = __fmaf_rn(w.x, fin[c4*4+0], a0);
            a1 = __fmaf_rn(w.y, fin[c4*4+1], a1);
            a2 = __fmaf_rn(w.z, fin[c4*4+2], a2);
            a3 = __fmaf_rn(w.w, fin[c4*4+3], a3);
        }
        float acc = ((a0 + a1) + (a2 + a3)) + bouts[co];
        acc = (acc >= 0.f) ? acc : 0.1f * acc;
        outb[(size_t)co * QPB] = acc;
    }
}

extern "C" void kernel_launch(void* const* d_in, const int* in_sizes, int n_in,
                              void* d_out, int out_size) {
    const float* uv    = (const float*)d_in[0];
    const float* feat  = (const float*)d_in[1];
    // d_in[2] = image_h, d_in[3] = image_w (shapes hardcoded for this problem)
    const float* w1    = (const float*)d_in[4];
    const float* b1    = (const float*)d_in[5];
    const float* w2    = (const float*)d_in[6];
    const float* b2    = (const float*)d_in[7];
    const float* w_out = (const float*)d_in[8];
    const float* b_out = (const float*)d_in[9];
    float* out = (float*)d_out;

    k_transpose<<<(BS * CH * NP + TPB - 1) / TPB, TPB>>>(feat);

    cudaFuncSetAttribute(k_main, cudaFuncAttributeMaxDynamicSharedMemorySize, SMEM_BYTES);
    dim3 grid(QPB / TPB, BS);
    k_main<<<grid, TPB, SMEM_BYTES>>>(uv, w1, b1, w2, b2, w_out, b_out, out);
}

// round 2
// speedup vs baseline: 2.3751x; 2.3751x over previous
#include <cuda_runtime.h>
#include <math.h>

#define BS   2
#define NP   4096
#define CH   64
#define IMH  128
#define IMW  256
#define QPB  (IMH*IMW)
#define TPB  256
#define BSZ  8
#define NBX  (IMW/BSZ)     // 32
#define NBY  (IMH/BSZ)     // 16
#define NBINS (NBX*NBY)    // 512
#define CAND_MAX 1024

// Scratch (static device arrays: no allocation).
__device__ float  g_featT[BS * NP * CH];    // [b][point][channel]
__device__ float4 g_binned[BS * NP];        // (px, py, psq, idx-as-float), bin-sorted
__device__ int    g_binCount[BS * NBINS];
__device__ int    g_prefix[BS * (NBINS + 1)];
__device__ int    g_fill[BS * NBINS];

__global__ void k_zero() {
    int i = blockIdx.x * blockDim.x + threadIdx.x;
    if (i < BS * NBINS) g_binCount[i] = 0;
}

__global__ void k_count(const float* __restrict__ uv) {
    int idx = blockIdx.x * blockDim.x + threadIdx.x;
    if (idx >= BS * NP) return;
    int b = idx >> 12, i = idx & (NP - 1);
    const float* uvb = uv + b * 2 * NP;
    float px = uvb[i], py = uvb[NP + i];
    int bx = min(max((int)(px * (1.0f / BSZ)), 0), NBX - 1);
    int by = min(max((int)(py * (1.0f / BSZ)), 0), NBY - 1);
    atomicAdd(&g_binCount[b * NBINS + by * NBX + bx], 1);
}

__global__ void k_scan() {   // one block per batch, NBINS threads
    __shared__ int s[NBINS];
    int b = blockIdx.x, t = threadIdx.x;
    int v = g_binCount[b * NBINS + t];
    s[t] = v;
    __syncthreads();
    for (int d = 1; d < NBINS; d <<= 1) {
        int add = (t >= d) ? s[t - d] : 0;
        __syncthreads();
        s[t] += add;
        __syncthreads();
    }
    g_prefix[b * (NBINS + 1) + t + 1] = s[t];
    g_fill[b * NBINS + t] = s[t] - v;          // exclusive prefix = write cursor
    if (t == 0) g_prefix[b * (NBINS + 1)] = 0;
}

__global__ void k_scatter(const float* __restrict__ uv) {
    int idx = blockIdx.x * blockDim.x + threadIdx.x;
    if (idx >= BS * NP) return;
    int b = idx >> 12, i = idx & (NP - 1);
    const float* uvb = uv + b * 2 * NP;
    float px = uvb[i], py = uvb[NP + i];
    float psq = __fadd_rn(__fmul_rn(px, px), __fmul_rn(py, py));  // reference rounding
    int bx = min(max((int)(px * (1.0f / BSZ)), 0), NBX - 1);
    int by = min(max((int)(py * (1.0f / BSZ)), 0), NBY - 1);
    int pos = atomicAdd(&g_fill[b * NBINS + by * NBX + bx], 1);
    g_binned[b * NP + pos] = make_float4(px, py, psq, __int_as_float(i));
}

__global__ void k_transpose(const float* __restrict__ feat) {
    int idx = blockIdx.x * blockDim.x + threadIdx.x;   // over BS*CH*NP
    if (idx >= BS * CH * NP) return;
    int b = idx / (CH * NP);
    int r = idx - b * (CH * NP);
    int c = r >> 12;
    int i = r & (NP - 1);
    g_featT[(b * NP + i) * CH + c] = feat[idx];
}

// lexicographic top-3 insertion: matches lax.top_k stability regardless of scan order
#define UPD(pp) {                                                              \
    float cr = __fmaf_rn((pp).y, gy, __fmul_rn((pp).x, gx));                   \
    float dd = __fsub_rn(__fadd_rn(qsq, (pp).z), __fadd_rn(cr, cr));           \
    int   pi = __float_as_int((pp).w);                                         \
    if (dd < d2b || (dd == d2b && pi < i2)) {                                  \
        if (dd < d1 || (dd == d1 && pi < i1)) {                                \
            d2b = d1; i2 = i1;                                                 \
            if (dd < d0 || (dd == d0 && pi < i0)) { d1 = d0; i1 = i0; d0 = dd; i0 = pi; } \
            else                                  { d1 = dd; i1 = pi; }        \
        } else { d2b = dd; i2 = pi; }                                          \
    } }

#define SMEM_FLOATS (CAND_MAX*4 + CH*CH + CH*3 + CH + CH + 9 + 3)
#define SMEM_BYTES  (SMEM_FLOATS * 4)

__global__ __launch_bounds__(TPB, 2)
void k_main(const float* __restrict__ uv,
            const float* __restrict__ w1, const float* __restrict__ b1,
            const float* __restrict__ w2, const float* __restrict__ b2,
            const float* __restrict__ w_out, const float* __restrict__ b_out,
            float* __restrict__ out)
{
    extern __shared__ float sm[];
    float4* cand  = (float4*)sm;
    float*  wouts = sm + CAND_MAX * 4;
    float*  w2s   = wouts + CH * CH;
    float*  b2s   = w2s + CH * 3;
    float*  bouts = b2s + CH;
    float*  w1s   = bouts + CH;
    float*  b1s   = w1s + 9;
    __shared__ int s_start[3], s_cnt[3], s_off[3], s_total;

    const int tid = threadIdx.x;
    const int b   = blockIdx.z;
    const int tx  = tid & 31, ty = tid >> 5;
    const int gxi = blockIdx.x * 32 + tx;
    const int gyi = blockIdx.y * 8 + ty;
    const int q   = gyi * IMW + gxi;
    const float gx = (float)gxi, gy = (float)gyi;
    const float qsq = gx * gx + gy * gy;   // exact for integer coords

    // candidate region: tile bins +/- 1
    const int tbx0 = blockIdx.x * 4;
    const int tby0 = blockIdx.y;
    const int bxlo = max(tbx0 - 1, 0), bxhi = min(tbx0 + 4, NBX - 1);
    const int bylo = max(tby0 - 1, 0), byhi = min(tby0 + 1, NBY - 1);
    const int nrows = byhi - bylo + 1;

    if (tid < nrows) {
        int row = bylo + tid;
        int s = g_prefix[b * (NBINS + 1) + row * NBX + bxlo];
        int e = g_prefix[b * (NBINS + 1) + row * NBX + bxhi + 1];
        s_start[tid] = s; s_cnt[tid] = e - s;
    }
    for (int i = tid; i < CH * CH; i += TPB) wouts[i] = w_out[i];
    if (tid < CH * 3) w2s[tid] = w2[tid];
    if (tid < CH) { b2s[tid] = b2[tid]; bouts[tid] = b_out[tid]; }
    if (tid < 9)  w1s[tid] = w1[tid];
    if (tid < 3)  b1s[tid] = b1[tid];
    __syncthreads();
    if (tid == 0) {
        int off = 0;
        for (int r = 0; r < nrows; ++r) { s_off[r] = off; off += s_cnt[r]; }
        s_total = off;
    }
    __syncthreads();
    const int total = s_total;
    const bool ovf = total > CAND_MAX;
    if (!ovf) {
        for (int r = 0; r < nrows; ++r) {    // 3 contiguous, coalesced ranges
            int c = s_cnt[r], st = s_start[r], of = s_off[r];
            for (int i = tid; i < c; i += TPB) cand[of + i] = g_binned[b * NP + st + i];
        }
    }
    __syncthreads();

    // ---- KNN over local candidates ----
    float d0 = INFINITY, d1 = INFINITY, d2b = INFINITY;
    int   i0 = 0x7fffffff, i1 = 0x7fffffff, i2 = 0x7fffffff;
    if (!ovf) {
        #pragma unroll 4
        for (int j = 0; j < total; ++j) { float4 p = cand[j]; UPD(p); }
    }
    // completeness guarantee: excluded points are >= dmin away
    float dl = (bxlo > 0)       ? (gx - (float)(bxlo * BSZ))       : 1e9f;
    float dr = (bxhi < NBX - 1) ? ((float)((bxhi + 1) * BSZ) - gx) : 1e9f;
    float dt = (bylo > 0)       ? (gy - (float)(bylo * BSZ))       : 1e9f;
    float db = (byhi < NBY - 1) ? ((float)((byhi + 1) * BSZ) - gy) : 1e9f;
    float dmin = fminf(fminf(dl, dr), fminf(dt, db));
    if (ovf || !(d2b + 0.25f <= dmin * dmin)) {   // rare fallback: exact brute force
        d0 = d1 = d2b = INFINITY; i0 = i1 = i2 = 0x7fffffff;
        const float4* gp = g_binned + b * NP;
        #pragma unroll 4
        for (int j = 0; j < NP; ++j) { float4 p = gp[j]; UPD(p); }
    }

    // ---- score MLP + feature gather ----
    float fin[CH];
    #pragma unroll
    for (int c = 0; c < CH; ++c) fin[c] = 0.f;

    const float* uvb = uv + b * 2 * NP;
    int nidx[3] = { i0, i1, i2 };
    #pragma unroll
    for (int k = 0; k < 3; ++k) {
        int id = nidx[k];
        float px = uvb[id], py = uvb[NP + id];
        float dx = __fsub_rn(px, gx);
        float dy = __fsub_rn(py, gy);
        float nrm = __fsqrt_rn(__fadd_rn(__fmul_rn(dx, dx), __fmul_rn(dy, dy)));
        float h[3];
        #pragma unroll
        for (int j = 0; j < 3; ++j) {
            float t = __fmaf_rn(w1s[j*3+2], nrm,
                      __fmaf_rn(w1s[j*3+1], dy, __fmul_rn(w1s[j*3+0], dx)));
            t = t + b1s[j];
            h[j] = (t >= 0.f) ? t : 0.1f * t;
        }
        const float4* fr = (const float4*)(g_featT + ((b * NP + id) << 6));
        #pragma unroll
        for (int c4 = 0; c4 < CH / 4; ++c4) {
            float4 f = fr[c4];
            #pragma unroll
            for (int jj = 0; jj < 4; ++jj) {
                int c = c4 * 4 + jj;
                float z = __fmaf_rn(w2s[c*3+2], h[2],
                          __fmaf_rn(w2s[c*3+1], h[1], __fmul_rn(w2s[c*3+0], h[0])));
                z = z + b2s[c];
                float s = __fdividef(1.f, 1.f + __expf(-z));
                float fv = (jj == 0) ? f.x : (jj == 1) ? f.y : (jj == 2) ? f.z : f.w;
                fin[c] = __fmaf_rn(s, fv, fin[c]);
            }
        }
    }

    // ---- fused 64x64 out-conv + leaky, coalesced writes ----
    float* outb = out + ((size_t)b * CH) * QPB + q;
    for (int co = 0; co < CH; ++co) {
        const float4* wr = (const float4*)(wouts + co * CH);
        float a0 = 0.f, a1 = 0.f, a2 = 0.f, a3 = 0.f;
        #pragma unroll
        for (int c4 = 0; c4 < CH / 4; ++c4) {
            float4 w = wr[c4];
            a0 = __fmaf_rn(w.x, fin[c4*4+0], a0);
            a1 = __fmaf_rn(w.y, fin[c4*4+1], a1);
            a2 = __fmaf_rn(w.z, fin[c4*4+2], a2);
            a3 = __fmaf_rn(w.w, fin[c4*4+3], a3);
        }
        float acc = ((a0 + a1) + (a2 + a3)) + bouts[co];
        acc = (acc >= 0.f) ? acc : 0.1f * acc;
        outb[(size_t)co * QPB] = acc;
    }
}

extern "C" void kernel_launch(void* const* d_in, const int* in_sizes, int n_in,
                              void* d_out, int out_size) {
    const float* uv    = (const float*)d_in[0];
    const float* feat  = (const float*)d_in[1];
    const float* w1    = (const float*)d_in[4];
    const float* b1    = (const float*)d_in[5];
    const float* w2    = (const float*)d_in[6];
    const float* b2    = (const float*)d_in[7];
    const float* w_out = (const float*)d_in[8];
    const float* b_out = (const float*)d_in[9];
    float* out = (float*)d_out;

    k_zero<<<(BS * NBINS + TPB - 1) / TPB, TPB>>>();
    k_count<<<(BS * NP + TPB - 1) / TPB, TPB>>>(uv);
    k_scan<<<BS, NBINS>>>();
    k_scatter<<<(BS * NP + TPB - 1) / TPB, TPB>>>(uv);
    k_transpose<<<(BS * CH * NP + TPB - 1) / TPB, TPB>>>(feat);

    cudaFuncSetAttribute(k_main, cudaFuncAttributeMaxDynamicSharedMemorySize, SMEM_BYTES);
    dim3 grid(IMW / 32, IMH / 8, BS);
    k_main<<<grid, TPB, SMEM_BYTES>>>(uv, w1, b1, w2, b2, w_out, b_out, out);
}

// round 3
// speedup vs baseline: 3.0822x; 1.2977x over previous
#include <cuda_runtime.h>
#include <math.h>

#define BS   2
#define NP   4096
#define CH   64
#define IMH  128
#define IMW  256
#define QPB  (IMH*IMW)
#define TPB  256
#define BSZ  8
#define NBX  (IMW/BSZ)     // 32
#define NBY  (IMH/BSZ)     // 16
#define NBINS (NBX*NBY)    // 512
#define CAND_MAX 768       // expected ~144 candidates; fallback covers overflow

typedef unsigned long long ull;

// Scratch (static device arrays: no allocation).
__device__ float  g_featT[BS * NP * CH];    // [b][point][channel]
__device__ float4 g_binned[BS * NP];        // (px, py, psq, idx-as-float), bin-sorted
__device__ int    g_prefix[BS * (NBINS + 1)];

// ---- packed f32x2 helpers ----
__device__ __forceinline__ ull pk2(float lo, float hi) {
    ull r; asm("mov.b64 %0,{%1,%2};" : "=l"(r) : "f"(lo), "f"(hi)); return r;
}
__device__ __forceinline__ void upk2(float& lo, float& hi, ull v) {
    asm("mov.b64 {%0,%1},%2;" : "=f"(lo), "=f"(hi) : "l"(v));
}
__device__ __forceinline__ ull fma2_(ull a, ull b, ull c) {
    ull d; asm("fma.rn.f32x2 %0,%1,%2,%3;" : "=l"(d) : "l"(a), "l"(b), "l"(c)); return d;
}
__device__ __forceinline__ ull mul2_(ull a, ull b) {
    ull d; asm("mul.rn.f32x2 %0,%1,%2;" : "=l"(d) : "l"(a), "l"(b)); return d;
}
__device__ __forceinline__ ull add2_(ull a, ull b) {
    ull d; asm("add.rn.f32x2 %0,%1,%2;" : "=l"(d) : "l"(a), "l"(b)); return d;
}
__device__ __forceinline__ ull sub2_(ull a, ull b) {
    ull d; asm("sub.rn.f32x2 %0,%1,%2;" : "=l"(d) : "l"(a), "l"(b)); return d;
}
__device__ __forceinline__ float tanh_ap(float x) {
    float y; asm("tanh.approx.f32 %0,%1;" : "=f"(y) : "f"(x)); return y;
}

// ============================================================================
// k_prep: blocks [0,BS) do per-batch binning (count/scan/scatter in SMEM);
//         blocks [BS, BS+BS*NP/64) do SMEM-tiled feature transpose.
// ============================================================================
__global__ __launch_bounds__(512, 1)
void k_prep(const float* __restrict__ uv, const float* __restrict__ feat) {
    __shared__ int s_cnt[NBINS];
    __shared__ int s_pfx[NBINS];
    __shared__ float s_tile[64][65];
    const int t = threadIdx.x;
    const int bid = blockIdx.x;

    if (bid < BS) {
        // ---- binning for batch bid ----
        const int b = bid;
        s_cnt[t] = 0;
        __syncthreads();
        const float* uvb = uv + b * 2 * NP;
        float4 myp[8]; int mybin[8];
        #pragma unroll
        for (int r = 0; r < 8; ++r) {
            int i = t + r * 512;
            float px = uvb[i], py = uvb[NP + i];
            float psq = __fadd_rn(__fmul_rn(px, px), __fmul_rn(py, py)); // ref rounding
            int bx = min(max((int)(px * (1.0f / BSZ)), 0), NBX - 1);
            int by = min(max((int)(py * (1.0f / BSZ)), 0), NBY - 1);
            mybin[r] = by * NBX + bx;
            myp[r] = make_float4(px, py, psq, __int_as_float(i));
            atomicAdd(&s_cnt[mybin[r]], 1);
        }
        __syncthreads();
        int v = s_cnt[t];
        s_pfx[t] = v;
        __syncthreads();
        for (int d = 1; d < NBINS; d <<= 1) {          // inclusive scan
            int add = (t >= d) ? s_pfx[t - d] : 0;
            __syncthreads();
            s_pfx[t] += add;
            __syncthreads();
        }
        g_prefix[b * (NBINS + 1) + t + 1] = s_pfx[t];
        if (t == 0) g_prefix[b * (NBINS + 1)] = 0;
        s_cnt[t] = s_pfx[t] - v;                       // exclusive prefix = cursor
        __syncthreads();
        #pragma unroll
        for (int r = 0; r < 8; ++r) {
            int pos = atomicAdd(&s_cnt[mybin[r]], 1);
            g_binned[b * NP + pos] = myp[r];
        }
    } else {
        // ---- transpose one 64ch x 64pt tile ----
        int tb = bid - BS;
        int b  = tb >> 6;            // NP/64 = 64 tiles per batch
        int i0 = (tb & 63) * 64;
        int c  = t >> 3, j = t & 7;
        #pragma unroll
        for (int rep = 0; rep < 2; ++rep) {
            int i4 = j + rep * 8;
            float4 v = *(const float4*)(feat + ((size_t)(b * CH + c) * NP + i0 + i4 * 4));
            s_tile[i4 * 4 + 0][c] = v.x;
            s_tile[i4 * 4 + 1][c] = v.y;
            s_tile[i4 * 4 + 2][c] = v.z;
            s_tile[i4 * 4 + 3][c] = v.w;
        }
        __syncthreads();
        int i = t >> 3;
        #pragma unroll
        for (int rep = 0; rep < 2; ++rep) {
            int c4 = j + rep * 8;
            float4 w;
            w.x = s_tile[i][c4 * 4 + 0];
            w.y = s_tile[i][c4 * 4 + 1];
            w.z = s_tile[i][c4 * 4 + 2];
            w.w = s_tile[i][c4 * 4 + 3];
            *(float4*)(g_featT + ((size_t)(b * NP + i0 + i) << 6) + c4 * 4) = w;
        }
    }
}

// lexicographic top-3 insertion (tie: lower original index), matches lax.top_k
#define INSERT(dd, pi) {                                                       \
    if ((dd) < d2b || ((dd) == d2b && (pi) < i2)) {                            \
        if ((dd) < d1 || ((dd) == d1 && (pi) < i1)) {                          \
            d2b = d1; i2 = i1;                                                 \
            if ((dd) < d0 || ((dd) == d0 && (pi) < i0)) { d1 = d0; i1 = i0; d0 = (dd); i0 = (pi); } \
            else                                        { d1 = (dd); i1 = (pi); } \
        } else { d2b = (dd); i2 = (pi); }                                      \
    } }

// SMEM (floats): candPx/Py/Psq/Idx[768 each] + wouts[4096] + w2a/b/c,b2,bout[64 each] + w1[16]+b1[8]
#define SM_PX    0
#define SM_PY    (SM_PX + CAND_MAX)
#define SM_PSQ   (SM_PY + CAND_MAX)
#define SM_IDX   (SM_PSQ + CAND_MAX)
#define SM_WOUT  (SM_IDX + CAND_MAX)
#define SM_W2A   (SM_WOUT + CH*CH)
#define SM_W2B   (SM_W2A + CH)
#define SM_W2C   (SM_W2B + CH)
#define SM_B2    (SM_W2C + CH)
#define SM_BOUT  (SM_B2 + CH)
#define SM_W1    (SM_BOUT + CH)
#define SM_B1    (SM_W1 + 16)
#define SMEM_FLOATS (SM_B1 + 8)
#define SMEM_BYTES  (SMEM_FLOATS * 4)

__global__ __launch_bounds__(TPB, 2)
void k_main(const float* __restrict__ uv,
            const float* __restrict__ w1, const float* __restrict__ b1,
            const float* __restrict__ w2, const float* __restrict__ b2,
            const float* __restrict__ w_out, const float* __restrict__ b_out,
            float* __restrict__ out)
{
    extern __shared__ float sm[];
    float* candPx  = sm + SM_PX;
    float* candPy  = sm + SM_PY;
    float* candPsq = sm + SM_PSQ;
    int*   candIdx = (int*)(sm + SM_IDX);
    float* wouts   = sm + SM_WOUT;
    float* w2aF = sm + SM_W2A; float* w2bF = sm + SM_W2B; float* w2cF = sm + SM_W2C;
    float* b2F  = sm + SM_B2;  float* boutF = sm + SM_BOUT;
    float* w1s = sm + SM_W1;   float* b1s = sm + SM_B1;
    __shared__ int s_start[3], s_cnt[3], s_off[3], s_total;

    const int tid = threadIdx.x;
    const int b   = blockIdx.z;
    const int tx  = tid & 31, ty = tid >> 5;
    const int gxi = blockIdx.x * 32 + tx;
    const int gyi = blockIdx.y * 8 + ty;
    const int q   = gyi * IMW + gxi;
    const float gx = (float)gxi, gy = (float)gyi;
    const float qsq = gx * gx + gy * gy;          // exact for integer coords

    // candidate bin region: tile bins +/- 1
    const int tbx0 = blockIdx.x * 4;
    const int tby0 = blockIdx.y;
    const int bxlo = max(tbx0 - 1, 0), bxhi = min(tbx0 + 4, NBX - 1);
    const int bylo = max(tby0 - 1, 0), byhi = min(tby0 + 1, NBY - 1);
    const int nrows = byhi - bylo + 1;

    if (tid < nrows) {
        int row = bylo + tid;
        int s = g_prefix[b * (NBINS + 1) + row * NBX + bxlo];
        int e = g_prefix[b * (NBINS + 1) + row * NBX + bxhi + 1];
        s_start[tid] = s; s_cnt[tid] = e - s;
    }
    for (int i = tid; i < CH * CH; i += TPB) wouts[i] = w_out[i];
    if (tid < CH) {
        w2aF[tid] = w2[tid * 3 + 0];
        w2bF[tid] = w2[tid * 3 + 1];
        w2cF[tid] = w2[tid * 3 + 2];
        b2F[tid]  = b2[tid];
        boutF[tid] = b_out[tid];
    }
    if (tid < 9) w1s[tid] = w1[tid];
    if (tid < 3) b1s[tid] = b1[tid];
    __syncthreads();
    if (tid == 0) {
        int off = 0;
        for (int r = 0; r < nrows; ++r) { s_off[r] = off; off += s_cnt[r]; }
        s_total = off;
    }
    __syncthreads();
    const int total = s_total;
    const bool ovf = total > CAND_MAX;
    if (!ovf) {
        for (int r = 0; r < nrows; ++r) {      // contiguous coalesced ranges -> SoA
            int c = s_cnt[r], st = s_start[r], of = s_off[r];
            for (int i = tid; i < c; i += TPB) {
                float4 p = g_binned[b * NP + st + i];
                candPx[of + i] = p.x; candPy[of + i] = p.y;
                candPsq[of + i] = p.z; candIdx[of + i] = __float_as_int(p.w);
            }
        }
    }
    __syncthreads();

    // ---- Phase 1: KNN over local candidates, packed f32x2 distances ----
    float d0 = INFINITY, d1 = INFINITY, d2b = INFINITY;
    int   i0 = 0x7fffffff, i1 = 0x7fffffff, i2 = 0x7fffffff;
    if (!ovf) {
        const ull* px2  = (const ull*)candPx;
        const ull* py2  = (const ull*)candPy;
        const ull* psq2 = (const ull*)candPsq;
        const ull gx2 = pk2(gx, gx), gy2 = pk2(gy, gy), qsq2 = pk2(qsq, qsq);
        int npair = total >> 1;
        #pragma unroll 4
        for (int jp = 0; jp < npair; ++jp) {
            ull cr2 = fma2_(py2[jp], gy2, mul2_(px2[jp], gx2));
            ull dd2 = sub2_(add2_(qsq2, psq2[jp]), add2_(cr2, cr2));
            float dda, ddb; upk2(dda, ddb, dd2);
            if (dda <= d2b) { int pi = candIdx[2 * jp];     INSERT(dda, pi); }
            if (ddb <= d2b) { int pi = candIdx[2 * jp + 1]; INSERT(ddb, pi); }
        }
        if (total & 1) {
            int j = total - 1;
            float cr = __fmaf_rn(candPy[j], gy, __fmul_rn(candPx[j], gx));
            float dd = __fsub_rn(__fadd_rn(qsq, candPsq[j]), __fadd_rn(cr, cr));
            if (dd <= d2b) { int pi = candIdx[j]; INSERT(dd, pi); }
        }
    }
    // completeness: any excluded point is >= dmin away
    float dl = (bxlo > 0)       ? (gx - (float)(bxlo * BSZ))       : 1e9f;
    float dr = (bxhi < NBX - 1) ? ((float)((bxhi + 1) * BSZ) - gx) : 1e9f;
    float dt = (bylo > 0)       ? (gy - (float)(bylo * BSZ))       : 1e9f;
    float db = (byhi < NBY - 1) ? ((float)((byhi + 1) * BSZ) - gy) : 1e9f;
    float dmin = fminf(fminf(dl, dr), fminf(dt, db));
    if (ovf || !(d2b + 0.25f <= dmin * dmin)) {    // rare exact fallback
        d0 = d1 = d2b = INFINITY; i0 = i1 = i2 = 0x7fffffff;
        const float4* gp = g_binned + b * NP;
        #pragma unroll 4
        for (int j = 0; j < NP; ++j) {
            float4 p = gp[j];
            float cr = __fmaf_rn(p.y, gy, __fmul_rn(p.x, gx));
            float dd = __fsub_rn(__fadd_rn(qsq, p.z), __fadd_rn(cr, cr));
            if (dd <= d2b) { int pi = __float_as_int(p.w); INSERT(dd, pi); }
        }
    }

    // ---- Phase 2: score MLP + gather, packed ----
    ull fin2[CH / 2];
    #pragma unroll
    for (int c = 0; c < CH / 2; ++c) fin2[c] = 0ull;

    const ull HALF2 = 0x3F0000003F000000ULL;   // (0.5f, 0.5f)
    const ull* w2a2 = (const ull*)w2aF;
    const ull* w2b2 = (const ull*)w2bF;
    const ull* w2c2 = (const ull*)w2cF;
    const ull* b2p2 = (const ull*)b2F;
    const float* uvb = uv + b * 2 * NP;
    int nidx[3] = { i0, i1, i2 };
    #pragma unroll
    for (int k = 0; k < 3; ++k) {
        int id = nidx[k];
        float px = uvb[id], py = uvb[NP + id];
        float dx = __fsub_rn(px, gx);
        float dy = __fsub_rn(py, gy);
        float nrm = __fsqrt_rn(__fadd_rn(__fmul_rn(dx, dx), __fmul_rn(dy, dy)));
        float h[3];
        #pragma unroll
        for (int j = 0; j < 3; ++j) {
            float t = __fmaf_rn(w1s[j*3+2], nrm,
                      __fmaf_rn(w1s[j*3+1], dy, __fmul_rn(w1s[j*3+0], dx)));
            t = t + b1s[j];
            h[j] = (t >= 0.f) ? t : 0.1f * t;
        }
        ull h0p = pk2(h[0], h[0]), h1p = pk2(h[1], h[1]), h2p = pk2(h[2], h[2]);
        const ulonglong2* fr = (const ulonglong2*)(g_featT + ((size_t)(b * NP + id) << 6));
        #pragma unroll
        for (int c8 = 0; c8 < 16; ++c8) {
            ulonglong2 f = fr[c8];
            {
                int c2 = 2 * c8;
                ull z2 = add2_(fma2_(w2c2[c2], h2p,
                               fma2_(w2b2[c2], h1p, mul2_(w2a2[c2], h0p))), b2p2[c2]);
                z2 = mul2_(z2, HALF2);
                float z0, z1; upk2(z0, z1, z2);
                float s0 = __fmaf_rn(0.5f, tanh_ap(z0), 0.5f);
                float s1 = __fmaf_rn(0.5f, tanh_ap(z1), 0.5f);
                fin2[c2] = fma2_(pk2(s0, s1), f.x, fin2[c2]);
            }
            {
                int c2 = 2 * c8 + 1;
                ull z2 = add2_(fma2_(w2c2[c2], h2p,
                               fma2_(w2b2[c2], h1p, mul2_(w2a2[c2], h0p))), b2p2[c2]);
                z2 = mul2_(z2, HALF2);
                float z0, z1; upk2(z0, z1, z2);
                float s0 = __fmaf_rn(0.5f, tanh_ap(z0), 0.5f);
                float s1 = __fmaf_rn(0.5f, tanh_ap(z1), 0.5f);
                fin2[c2] = fma2_(pk2(s0, s1), f.y, fin2[c2]);
            }
        }
    }

    // ---- Phase 3: 64x64 out-conv with FFMA2, coalesced writes ----
    float* outb = out + ((size_t)b * CH) * QPB + q;
    for (int co = 0; co < CH; ++co) {
        const ulonglong2* wr = (const ulonglong2*)(wouts + co * CH);
        ull a0 = 0, a1 = 0, a2 = 0, a3 = 0;
        #pragma unroll
        for (int c4 = 0; c4 < 16; c4 += 2) {
            ulonglong2 wA = wr[c4], wB = wr[c4 + 1];
            a0 = fma2_(wA.x, fin2[2*c4 + 0], a0);
            a1 = fma2_(wA.y, fin2[2*c4 + 1], a1);
            a2 = fma2_(wB.x, fin2[2*c4 + 2], a2);
            a3 = fma2_(wB.y, fin2[2*c4 + 3], a3);
        }
        ull s2 = add2_(add2_(a0, a1), add2_(a2, a3));
        float lo, hi; upk2(lo, hi, s2);
        float acc = (lo + hi) + boutF[co];
        acc = (acc >= 0.f) ? acc : 0.1f * acc;
        outb[(size_t)co * QPB] = acc;
    }
}

extern "C" void kernel_launch(void* const* d_in, const int* in_sizes, int n_in,
                              void* d_out, int out_size) {
    const float* uv    = (const float*)d_in[0];
    const float* feat  = (const float*)d_in[1];
    const float* w1    = (const float*)d_in[4];
    const float* b1    = (const float*)d_in[5];
    const float* w2    = (const float*)d_in[6];
    const float* b2    = (const float*)d_in[7];
    const float* w_out = (const float*)d_in[8];
    const float* b_out = (const float*)d_in[9];
    float* out = (float*)d_out;

    k_prep<<<BS + BS * (NP / 64), 512>>>(uv, feat);

    cudaFuncSetAttribute(k_main, cudaFuncAttributeMaxDynamicSharedMemorySize, SMEM_BYTES);
    dim3 grid(IMW / 32, IMH / 8, BS);
    k_main<<<grid, TPB, SMEM_BYTES>>>(uv, w1, b1, w2, b2, w_out, b_out, out);
}

// round 4
// speedup vs baseline: 3.4237x; 1.1108x over previous
#include <cuda_runtime.h>
#include <math.h>

#define BS   2
#define NP   4096
#define CH   64
#define IMH  128
#define IMW  256
#define QPB  (IMH*IMW)
#define TPB  256
#define BSZ  8
#define NBX  (IMW/BSZ)     // 32
#define NBY  (IMH/BSZ)     // 16
#define NBINS (NBX*NBY)    // 512
#define CAND_MAX 768
#define CPAD (CAND_MAX + 8)

typedef unsigned long long ull;

// Scratch (static device arrays: no allocation).
__device__ float  g_featT[BS * NP * CH];    // [b][point][channel]
__device__ float4 g_binned[BS * NP];        // (px, py, psq, idx-as-float), bin-sorted
__device__ int    g_prefix[BS * (NBINS + 1)];

// ---- packed f32x2 helpers ----
__device__ __forceinline__ ull pk2(float lo, float hi) {
    ull r; asm("mov.b64 %0,{%1,%2};" : "=l"(r) : "f"(lo), "f"(hi)); return r;
}
__device__ __forceinline__ void upk2(float& lo, float& hi, ull v) {
    asm("mov.b64 {%0,%1},%2;" : "=f"(lo), "=f"(hi) : "l"(v));
}
__device__ __forceinline__ ull fma2_(ull a, ull b, ull c) {
    ull d; asm("fma.rn.f32x2 %0,%1,%2,%3;" : "=l"(d) : "l"(a), "l"(b), "l"(c)); return d;
}
__device__ __forceinline__ ull mul2_(ull a, ull b) {
    ull d; asm("mul.rn.f32x2 %0,%1,%2;" : "=l"(d) : "l"(a), "l"(b)); return d;
}
__device__ __forceinline__ ull add2_(ull a, ull b) {
    ull d; asm("add.rn.f32x2 %0,%1,%2;" : "=l"(d) : "l"(a), "l"(b)); return d;
}
__device__ __forceinline__ ull sub2_(ull a, ull b) {
    ull d; asm("sub.rn.f32x2 %0,%1,%2;" : "=l"(d) : "l"(a), "l"(b)); return d;
}
__device__ __forceinline__ float tanh_ap(float x) {
    float y; asm("tanh.approx.f32 %0,%1;" : "=f"(y) : "f"(x)); return y;
}

// ============================================================================
// k_prep: blocks [0,BS) bin points (count/scan/scatter in SMEM);
//         blocks [BS, ...) transpose features in 64x64 SMEM tiles.
// ============================================================================
__global__ __launch_bounds__(512, 1)
void k_prep(const float* __restrict__ uv, const float* __restrict__ feat) {
    __shared__ int s_cnt[NBINS];
    __shared__ int s_pfx[NBINS];
    __shared__ float s_tile[64][65];
    const int t = threadIdx.x;
    const int bid = blockIdx.x;

    if (bid < BS) {
        const int b = bid;
        s_cnt[t] = 0;
        __syncthreads();
        const float* uvb = uv + b * 2 * NP;
        float4 myp[8]; int mybin[8];
        #pragma unroll
        for (int r = 0; r < 8; ++r) {
            int i = t + r * 512;
            float px = uvb[i], py = uvb[NP + i];
            float psq = __fadd_rn(__fmul_rn(px, px), __fmul_rn(py, py)); // ref rounding
            int bx = min(max((int)(px * (1.0f / BSZ)), 0), NBX - 1);
            int by = min(max((int)(py * (1.0f / BSZ)), 0), NBY - 1);
            mybin[r] = by * NBX + bx;
            myp[r] = make_float4(px, py, psq, __int_as_float(i));
            atomicAdd(&s_cnt[mybin[r]], 1);
        }
        __syncthreads();
        int v = s_cnt[t];
        s_pfx[t] = v;
        __syncthreads();
        for (int d = 1; d < NBINS; d <<= 1) {
            int add = (t >= d) ? s_pfx[t - d] : 0;
            __syncthreads();
            s_pfx[t] += add;
            __syncthreads();
        }
        g_prefix[b * (NBINS + 1) + t + 1] = s_pfx[t];
        if (t == 0) g_prefix[b * (NBINS + 1)] = 0;
        s_cnt[t] = s_pfx[t] - v;
        __syncthreads();
        #pragma unroll
        for (int r = 0; r < 8; ++r) {
            int pos = atomicAdd(&s_cnt[mybin[r]], 1);
            g_binned[b * NP + pos] = myp[r];
        }
    } else {
        int tb = bid - BS;
        int b  = tb >> 6;
        int i0 = (tb & 63) * 64;
        int c  = t >> 3, j = t & 7;
        #pragma unroll
        for (int rep = 0; rep < 2; ++rep) {
            int i4 = j + rep * 8;
            float4 v = *(const float4*)(feat + ((size_t)(b * CH + c) * NP + i0 + i4 * 4));
            s_tile[i4 * 4 + 0][c] = v.x;
            s_tile[i4 * 4 + 1][c] = v.y;
            s_tile[i4 * 4 + 2][c] = v.z;
            s_tile[i4 * 4 + 3][c] = v.w;
        }
        __syncthreads();
        int i = t >> 3;
        #pragma unroll
        for (int rep = 0; rep < 2; ++rep) {
            int c4 = j + rep * 8;
            float4 w;
            w.x = s_tile[i][c4 * 4 + 0];
            w.y = s_tile[i][c4 * 4 + 1];
            w.z = s_tile[i][c4 * 4 + 2];
            w.w = s_tile[i][c4 * 4 + 3];
            *(float4*)(g_featT + ((size_t)(b * NP + i0 + i) << 6) + c4 * 4) = w;
        }
    }
}

// lexicographic top-3 insertion (tie: lower original index) + slot tracking
#define INSERT(dd, pi, sl) {                                                   \
    if ((dd) < d2b || ((dd) == d2b && (pi) < i2)) {                            \
        if ((dd) < d1 || ((dd) == d1 && (pi) < i1)) {                          \
            d2b = d1; i2 = i1; s2 = s1;                                        \
            if ((dd) < d0 || ((dd) == d0 && (pi) < i0))                        \
                 { d1 = d0; i1 = i0; s1 = s0; d0 = (dd); i0 = (pi); s0 = (sl); } \
            else { d1 = (dd); i1 = (pi); s1 = (sl); }                          \
        } else { d2b = (dd); i2 = (pi); s2 = (sl); }                           \
    } }

#define SM_PX    0
#define SM_PY    (SM_PX + CPAD)
#define SM_PSQ   (SM_PY + CPAD)
#define SM_IDX   (SM_PSQ + CPAD)
#define SM_WOUT  (SM_IDX + CPAD)
#define SM_W2A   (SM_WOUT + CH*CH)
#define SM_W2B   (SM_W2A + CH)
#define SM_W2C   (SM_W2B + CH)
#define SM_B2    (SM_W2C + CH)
#define SM_BOUT  (SM_B2 + CH)
#define SM_W1    (SM_BOUT + CH)
#define SM_B1    (SM_W1 + 16)
#define SMEM_FLOATS (SM_B1 + 8)
#define SMEM_BYTES  (SMEM_FLOATS * 4)

__global__ __launch_bounds__(TPB, 2)
void k_main(const float* __restrict__ w1, const float* __restrict__ b1,
            const float* __restrict__ w2, const float* __restrict__ b2,
            const float* __restrict__ w_out, const float* __restrict__ b_out,
            float* __restrict__ out)
{
    extern __shared__ float sm[];
    float* candPx  = sm + SM_PX;
    float* candPy  = sm + SM_PY;
    float* candPsq = sm + SM_PSQ;
    int*   candIdx = (int*)(sm + SM_IDX);
    float* wouts   = sm + SM_WOUT;
    float* w2aF = sm + SM_W2A; float* w2bF = sm + SM_W2B; float* w2cF = sm + SM_W2C;
    float* b2F  = sm + SM_B2;  float* boutF = sm + SM_BOUT;
    float* w1s = sm + SM_W1;   float* b1s = sm + SM_B1;
    __shared__ int s_startA[3], s_cntA[3], s_offA[3], s_totalA;

    const int tid = threadIdx.x;
    const int b   = blockIdx.z;
    const int tx  = tid & 31, ty = tid >> 5;
    const int gxi = blockIdx.x * 32 + tx;
    const int gyi = blockIdx.y * 8 + ty;
    const int q   = gyi * IMW + gxi;
    const float gx = (float)gxi, gy = (float)gyi;
    const float qsq = gx * gx + gy * gy;          // exact for integer coords

    // candidate bin region: tile bins +/- 1
    const int tbx0 = blockIdx.x * 4;
    const int tby0 = blockIdx.y;
    const int bxlo = max(tbx0 - 1, 0), bxhi = min(tbx0 + 4, NBX - 1);
    const int bylo = max(tby0 - 1, 0), byhi = min(tby0 + 1, NBY - 1);
    const int nrows = byhi - bylo + 1;

    if (tid < nrows) {
        int row = bylo + tid;
        int s = g_prefix[b * (NBINS + 1) + row * NBX + bxlo];
        int e = g_prefix[b * (NBINS + 1) + row * NBX + bxhi + 1];
        s_startA[tid] = s; s_cntA[tid] = e - s;
    }
    for (int i = tid; i < CH * CH; i += TPB) wouts[i] = w_out[i];
    if (tid < CH) {
        w2aF[tid] = w2[tid * 3 + 0];
        w2bF[tid] = w2[tid * 3 + 1];
        w2cF[tid] = w2[tid * 3 + 2];
        b2F[tid]  = b2[tid];
        boutF[tid] = b_out[tid];
    }
    if (tid < 9) w1s[tid] = w1[tid];
    if (tid < 3) b1s[tid] = b1[tid];
    __syncthreads();
    if (tid == 0) {
        int off = 0;
        for (int r = 0; r < nrows; ++r) { s_offA[r] = off; off += s_cntA[r]; }
        s_totalA = off;
    }
    __syncthreads();
    const int total = s_totalA;
    const bool ovf = total > CAND_MAX;
    if (!ovf) {
        for (int r = 0; r < nrows; ++r) {      // contiguous coalesced ranges -> SoA
            int c = s_cntA[r], st = s_startA[r], of = s_offA[r];
            for (int i = tid; i < c; i += TPB) {
                float4 p = g_binned[b * NP + st + i];
                candPx[of + i] = p.x; candPy[of + i] = p.y;
                candPsq[of + i] = p.z; candIdx[of + i] = __float_as_int(p.w);
            }
        }
        if (tid < 8) {   // sentinel pad to a float4 boundary: huge dist, huge idx
            candPx[total + tid] = 0.f; candPy[total + tid] = 0.f;
            candPsq[total + tid] = 1e30f; candIdx[total + tid] = 0x7ffffff0;
        }
    }
    __syncthreads();

    // ---- Phase 1: KNN, 4 candidates per iteration via LDS.128 ----
    float d0 = INFINITY, d1 = INFINITY, d2b = INFINITY;
    int   i0 = 0x7fffffff, i1 = 0x7fffffff, i2 = 0x7fffffff;
    int   s0 = 0, s1 = 0, s2 = 0;
    bool  fb = false;
    if (!ovf) {
        const float4* px4  = (const float4*)candPx;
        const float4* py4  = (const float4*)candPy;
        const float4* psq4 = (const float4*)candPsq;
        const ull gx2 = pk2(gx, gx), gy2 = pk2(gy, gy), qsq2 = pk2(qsq, qsq);
        int nq = (total + 3) >> 2;
        #pragma unroll 2
        for (int jq = 0; jq < nq; ++jq) {
            float4 PX = px4[jq], PY = py4[jq], PSQ = psq4[jq];
            ull crA = fma2_(pk2(PY.x, PY.y), gy2, mul2_(pk2(PX.x, PX.y), gx2));
            ull ddA = sub2_(add2_(qsq2, pk2(PSQ.x, PSQ.y)), add2_(crA, crA));
            ull crB = fma2_(pk2(PY.z, PY.w), gy2, mul2_(pk2(PX.z, PX.w), gx2));
            ull ddB = sub2_(add2_(qsq2, pk2(PSQ.z, PSQ.w)), add2_(crB, crB));
            float a0, a1, a2, a3;
            upk2(a0, a1, ddA); upk2(a2, a3, ddB);
            int base = 4 * jq;
            if (a0 <= d2b) { int pi = candIdx[base + 0]; INSERT(a0, pi, base + 0); }
            if (a1 <= d2b) { int pi = candIdx[base + 1]; INSERT(a1, pi, base + 1); }
            if (a2 <= d2b) { int pi = candIdx[base + 2]; INSERT(a2, pi, base + 2); }
            if (a3 <= d2b) { int pi = candIdx[base + 3]; INSERT(a3, pi, base + 3); }
        }
    }
    // completeness: any excluded point is >= dmin away
    float dl = (bxlo > 0)       ? (gx - (float)(bxlo * BSZ))       : 1e9f;
    float dr = (bxhi < NBX - 1) ? ((float)((bxhi + 1) * BSZ) - gx) : 1e9f;
    float dt = (bylo > 0)       ? (gy - (float)(bylo * BSZ))       : 1e9f;
    float db = (byhi < NBY - 1) ? ((float)((byhi + 1) * BSZ) - gy) : 1e9f;
    float dmin = fminf(fminf(dl, dr), fminf(dt, db));
    if (ovf || !(d2b + 0.25f <= dmin * dmin)) {    // rare exact fallback
        fb = true;
        d0 = d1 = d2b = INFINITY; i0 = i1 = i2 = 0x7fffffff;
        const float4* gp = g_binned + b * NP;
        #pragma unroll 4
        for (int j = 0; j < NP; ++j) {
            float4 p = gp[j];
            float cr = __fmaf_rn(p.y, gy, __fmul_rn(p.x, gx));
            float dd = __fsub_rn(__fadd_rn(qsq, p.z), __fadd_rn(cr, cr));
            if (dd <= d2b) { int pi = __float_as_int(p.w); INSERT(dd, pi, j); }
        }
    }

    // ---- Phase 2: score MLP (precomputed) + pipelined gather ----
    ull fin2[CH / 2];
    #pragma unroll
    for (int c = 0; c < CH / 2; ++c) fin2[c] = 0ull;

    const ull HALF2 = 0x3F0000003F000000ULL;
    const ull* w2a2 = (const ull*)w2aF;
    const ull* w2b2 = (const ull*)w2bF;
    const ull* w2c2 = (const ull*)w2cF;
    const ull* b2p2 = (const ull*)b2F;

    int nidx[3] = { i0, i1, i2 };
    int nsl[3]  = { s0, s1, s2 };
    ull hp0[3], hp1[3], hp2[3];
    #pragma unroll
    for (int k = 0; k < 3; ++k) {
        float px, py;
        if (!fb) { px = candPx[nsl[k]]; py = candPy[nsl[k]]; }
        else     { float4 p = g_binned[b * NP + nsl[k]]; px = p.x; py = p.y; }
        float dx = __fsub_rn(px, gx);
        float dy = __fsub_rn(py, gy);
        float nrm = __fsqrt_rn(__fadd_rn(__fmul_rn(dx, dx), __fmul_rn(dy, dy)));
        float h[3];
        #pragma unroll
        for (int j = 0; j < 3; ++j) {
            float t = __fmaf_rn(w1s[j*3+2], nrm,
                      __fmaf_rn(w1s[j*3+1], dy, __fmul_rn(w1s[j*3+0], dx)));
            t = t + b1s[j];
            h[j] = (t >= 0.f) ? t : 0.1f * t;
        }
        hp0[k] = pk2(h[0], h[0]); hp1[k] = pk2(h[1], h[1]); hp2[k] = pk2(h[2], h[2]);
    }

    const ulonglong2* fr0 = (const ulonglong2*)(g_featT + ((size_t)(b * NP + nidx[0]) << 6));
    const ulonglong2* fr1 = (const ulonglong2*)(g_featT + ((size_t)(b * NP + nidx[1]) << 6));
    const ulonglong2* fr2 = (const ulonglong2*)(g_featT + ((size_t)(b * NP + nidx[2]) << 6));

    ulonglong2 fA = fr0[0], fB = fr1[0], fC = fr2[0];
    #pragma unroll 2
    for (int c8 = 0; c8 < 16; ++c8) {
        ulonglong2 nA, nB, nC;
        if (c8 < 15) { nA = fr0[c8+1]; nB = fr1[c8+1]; nC = fr2[c8+1]; }   // prefetch
        int c2 = 2 * c8;
        ull wa0 = w2a2[c2],   wb0 = w2b2[c2],   wc0 = w2c2[c2],   bb0 = b2p2[c2];
        ull wa1 = w2a2[c2+1], wb1 = w2b2[c2+1], wc1 = w2c2[c2+1], bb1 = b2p2[c2+1];
        #pragma unroll
        for (int k = 0; k < 3; ++k) {
            ulonglong2 f = (k == 0) ? fA : (k == 1) ? fB : fC;
            ull z0 = fma2_(wc0, hp2[k], fma2_(wb0, hp1[k], fma2_(wa0, hp0[k], bb0)));
            ull z1 = fma2_(wc1, hp2[k], fma2_(wb1, hp1[k], fma2_(wa1, hp0[k], bb1)));
            z0 = mul2_(z0, HALF2); z1 = mul2_(z1, HALF2);
            float za, zb, zc, zd;
            upk2(za, zb, z0); upk2(zc, zd, z1);
            float sa = __fmaf_rn(0.5f, tanh_ap(za), 0.5f);
            float sb = __fmaf_rn(0.5f, tanh_ap(zb), 0.5f);
            float sc = __fmaf_rn(0.5f, tanh_ap(zc), 0.5f);
            float sd = __fmaf_rn(0.5f, tanh_ap(zd), 0.5f);
            fin2[c2]     = fma2_(pk2(sa, sb), f.x, fin2[c2]);
            fin2[c2 + 1] = fma2_(pk2(sc, sd), f.y, fin2[c2 + 1]);
        }
        fA = nA; fB = nB; fC = nC;
    }

    // ---- Phase 3: 64x64 out-conv, co pairs, FFMA2, coalesced writes ----
    float* outb = out + ((size_t)b * CH) * QPB + q;
    #pragma unroll 2
    for (int co = 0; co < CH; co += 2) {
        const ulonglong2* wr0 = (const ulonglong2*)(wouts + co * CH);
        const ulonglong2* wr1 = (const ulonglong2*)(wouts + co * CH + CH);
        ull a0 = 0, a1 = 0, c0 = 0, c1 = 0;
        #pragma unroll
        for (int c4 = 0; c4 < 16; c4 += 2) {
            ulonglong2 wA = wr0[c4], wA2 = wr0[c4 + 1];
            ulonglong2 wB = wr1[c4], wB2 = wr1[c4 + 1];
            a0 = fma2_(wA.x,  fin2[2*c4 + 0], a0);
            a1 = fma2_(wA.y,  fin2[2*c4 + 1], a1);
            a0 = fma2_(wA2.x, fin2[2*c4 + 2], a0);
            a1 = fma2_(wA2.y, fin2[2*c4 + 3], a1);
            c0 = fma2_(wB.x,  fin2[2*c4 + 0], c0);
            c1 = fma2_(wB.y,  fin2[2*c4 + 1], c1);
            c0 = fma2_(wB2.x, fin2[2*c4 + 2], c0);
            c1 = fma2_(wB2.y, fin2[2*c4 + 3], c1);
        }
        ull sA = add2_(a0, a1), sB = add2_(c0, c1);
        float lo, hi, lo2, hi2;
        upk2(lo, hi, sA); upk2(lo2, hi2, sB);
        float accA = (lo + hi) + boutF[co];
        float accB = (lo2 + hi2) + boutF[co + 1];
        accA = (accA >= 0.f) ? accA : 0.1f * accA;
        accB = (accB >= 0.f) ? accB : 0.1f * accB;
        outb[(size_t)co * QPB] = accA;
        outb[(size_t)(co + 1) * QPB] = accB;
    }
}

extern "C" void kernel_launch(void* const* d_in, const int* in_sizes, int n_in,
                              void* d_out, int out_size) {
    const float* uv    = (const float*)d_in[0];
    const float* feat  = (const float*)d_in[1];
    const float* w1    = (const float*)d_in[4];
    const float* b1    = (const float*)d_in[5];
    const float* w2    = (const float*)d_in[6];
    const float* b2    = (const float*)d_in[7];
    const float* w_out = (const float*)d_in[8];
    const float* b_out = (const float*)d_in[9];
    float* out = (float*)d_out;

    k_prep<<<BS + BS * (NP / 64), 512>>>(uv, feat);

    cudaFuncSetAttribute(k_main, cudaFuncAttributeMaxDynamicSharedMemorySize, SMEM_BYTES);
    dim3 grid(IMW / 32, IMH / 8, BS);
    k_main<<<grid, TPB, SMEM_BYTES>>>(w1, b1, w2, b2, w_out, b_out, out);
}

// round 5
// speedup vs baseline: 3.6906x; 1.0780x over previous
#include <cuda_runtime.h>
#include <math.h>

#define BS   2
#define NP   4096
#define CH   64
#define IMH  128
#define IMW  256
#define QPB  (IMH*IMW)
#define TPB  128
#define BSZ  8
#define NBX  (IMW/BSZ)     // 32
#define NBY  (IMH/BSZ)     // 16
#define NBINS (NBX*NBY)    // 512
#define CAND_MAX 768
#define CPAD (CAND_MAX + 8)

typedef unsigned long long ull;

// Scratch (static device arrays: no allocation).
__device__ float  g_featT[BS * NP * CH];    // [b][point][channel]
__device__ float4 g_binned[BS * NP];        // (px, py, psq, idx-as-float), bin-sorted
__device__ int    g_prefix[BS * (NBINS + 1)];

// ---- packed f32x2 helpers ----
__device__ __forceinline__ ull pk2(float lo, float hi) {
    ull r; asm("mov.b64 %0,{%1,%2};" : "=l"(r) : "f"(lo), "f"(hi)); return r;
}
__device__ __forceinline__ void upk2(float& lo, float& hi, ull v) {
    asm("mov.b64 {%0,%1},%2;" : "=f"(lo), "=f"(hi) : "l"(v));
}
__device__ __forceinline__ ull fma2_(ull a, ull b, ull c) {
    ull d; asm("fma.rn.f32x2 %0,%1,%2,%3;" : "=l"(d) : "l"(a), "l"(b), "l"(c)); return d;
}
__device__ __forceinline__ ull mul2_(ull a, ull b) {
    ull d; asm("mul.rn.f32x2 %0,%1,%2;" : "=l"(d) : "l"(a), "l"(b)); return d;
}
__device__ __forceinline__ ull add2_(ull a, ull b) {
    ull d; asm("add.rn.f32x2 %0,%1,%2;" : "=l"(d) : "l"(a), "l"(b)); return d;
}
__device__ __forceinline__ ull sub2_(ull a, ull b) {
    ull d; asm("sub.rn.f32x2 %0,%1,%2;" : "=l"(d) : "l"(a), "l"(b)); return d;
}
__device__ __forceinline__ float tanh_ap(float x) {
    float y; asm("tanh.approx.f32 %0,%1;" : "=f"(y) : "f"(x)); return y;
}

// ============================================================================
// k_prep: blocks [0,BS) bin points (count/scan/scatter in SMEM);
//         blocks [BS, ...) transpose features in 64x64 SMEM tiles.
// ============================================================================
__global__ __launch_bounds__(512, 1)
void k_prep(const float* __restrict__ uv, const float* __restrict__ feat) {
    __shared__ int s_cnt[NBINS];
    __shared__ int s_pfx[NBINS];
    __shared__ float s_tile[64][65];
    const int t = threadIdx.x;
    const int bid = blockIdx.x;

    if (bid < BS) {
        const int b = bid;
        s_cnt[t] = 0;
        __syncthreads();
        const float* uvb = uv + b * 2 * NP;
        float4 myp[8]; int mybin[8];
        #pragma unroll
        for (int r = 0; r < 8; ++r) {
            int i = t + r * 512;
            float px = uvb[i], py = uvb[NP + i];
            float psq = __fadd_rn(__fmul_rn(px, px), __fmul_rn(py, py)); // ref rounding
            int bx = min(max((int)(px * (1.0f / BSZ)), 0), NBX - 1);
            int by = min(max((int)(py * (1.0f / BSZ)), 0), NBY - 1);
            mybin[r] = by * NBX + bx;
            myp[r] = make_float4(px, py, psq, __int_as_float(i));
            atomicAdd(&s_cnt[mybin[r]], 1);
        }
        __syncthreads();
        int v = s_cnt[t];
        s_pfx[t] = v;
        __syncthreads();
        for (int d = 1; d < NBINS; d <<= 1) {
            int add = (t >= d) ? s_pfx[t - d] : 0;
            __syncthreads();
            s_pfx[t] += add;
            __syncthreads();
        }
        g_prefix[b * (NBINS + 1) + t + 1] = s_pfx[t];
        if (t == 0) g_prefix[b * (NBINS + 1)] = 0;
        s_cnt[t] = s_pfx[t] - v;
        __syncthreads();
        #pragma unroll
        for (int r = 0; r < 8; ++r) {
            int pos = atomicAdd(&s_cnt[mybin[r]], 1);
            g_binned[b * NP + pos] = myp[r];
        }
    } else {
        int tb = bid - BS;
        int b  = tb >> 6;
        int i0 = (tb & 63) * 64;
        int c  = t >> 3, j = t & 7;
        #pragma unroll
        for (int rep = 0; rep < 2; ++rep) {
            int i4 = j + rep * 8;
            float4 v = *(const float4*)(feat + ((size_t)(b * CH + c) * NP + i0 + i4 * 4));
            s_tile[i4 * 4 + 0][c] = v.x;
            s_tile[i4 * 4 + 1][c] = v.y;
            s_tile[i4 * 4 + 2][c] = v.z;
            s_tile[i4 * 4 + 3][c] = v.w;
        }
        __syncthreads();
        int i = t >> 3;
        #pragma unroll
        for (int rep = 0; rep < 2; ++rep) {
            int c4 = j + rep * 8;
            float4 w;
            w.x = s_tile[i][c4 * 4 + 0];
            w.y = s_tile[i][c4 * 4 + 1];
            w.z = s_tile[i][c4 * 4 + 2];
            w.w = s_tile[i][c4 * 4 + 3];
            *(float4*)(g_featT + ((size_t)(b * NP + i0 + i) << 6) + c4 * 4) = w;
        }
    }
}

// lexicographic top-3 insertion (tie: lower original index) + slot tracking
#define INSERT(dd, pi, sl) {                                                   \
    if ((dd) < d2b || ((dd) == d2b && (pi) < i2)) {                            \
        if ((dd) < d1 || ((dd) == d1 && (pi) < i1)) {                          \
            d2b = d1; i2 = i1; s2 = s1;                                        \
            if ((dd) < d0 || ((dd) == d0 && (pi) < i0))                        \
                 { d1 = d0; i1 = i0; s1 = s0; d0 = (dd); i0 = (pi); s0 = (sl); } \
            else { d1 = (dd); i1 = (pi); s1 = (sl); }                          \
        } else { d2b = (dd); i2 = (pi); s2 = (sl); }                           \
    } }

#define SM_PX    0
#define SM_PY    (SM_PX + CPAD)
#define SM_PSQ   (SM_PY + CPAD)
#define SM_IDX   (SM_PSQ + CPAD)
#define SM_WOUT  (SM_IDX + CPAD)
#define SM_W2A   (SM_WOUT + CH*CH)
#define SM_W2B   (SM_W2A + CH)
#define SM_W2C   (SM_W2B + CH)
#define SM_B2    (SM_W2C + CH)
#define SM_BOUT  (SM_B2 + CH)
#define SM_W1    (SM_BOUT + CH)
#define SM_B1    (SM_W1 + 16)
#define SMEM_FLOATS (SM_B1 + 8)
#define SMEM_BYTES  (SMEM_FLOATS * 4)

__global__ __launch_bounds__(TPB, 5)
void k_main(const float* __restrict__ w1, const float* __restrict__ b1,
            const float* __restrict__ w2, const float* __restrict__ b2,
            const float* __restrict__ w_out, const float* __restrict__ b_out,
            float* __restrict__ out)
{
    extern __shared__ float sm[];
    float* candPx  = sm + SM_PX;
    float* candPy  = sm + SM_PY;
    float* candPsq = sm + SM_PSQ;
    int*   candIdx = (int*)(sm + SM_IDX);
    float* wouts   = sm + SM_WOUT;
    float* w2aF = sm + SM_W2A; float* w2bF = sm + SM_W2B; float* w2cF = sm + SM_W2C;
    float* b2F  = sm + SM_B2;  float* boutF = sm + SM_BOUT;
    float* w1s = sm + SM_W1;   float* b1s = sm + SM_B1;
    __shared__ int s_startA[3], s_cntA[3], s_offA[3], s_totalA;

    const int tid = threadIdx.x;
    const int b   = blockIdx.z;
    const int tx  = tid & 31, ty = tid >> 5;        // 32x4 pixel tile
    const int gxi = blockIdx.x * 32 + tx;
    const int gyi = blockIdx.y * 4 + ty;
    const int q   = gyi * IMW + gxi;
    const float gx = (float)gxi, gy = (float)gyi;
    const float qsq = gx * gx + gy * gy;            // exact for integer coords

    // candidate bin region: tile lies in one bin-row -> ring of <=3 rows, 6 cols
    const int tbx0 = blockIdx.x * 4;
    const int tby0 = blockIdx.y >> 1;
    const int bxlo = max(tbx0 - 1, 0), bxhi = min(tbx0 + 4, NBX - 1);
    const int bylo = max(tby0 - 1, 0), byhi = min(tby0 + 1, NBY - 1);
    const int nrows = byhi - bylo + 1;

    if (tid < nrows) {
        int row = bylo + tid;
        int s = g_prefix[b * (NBINS + 1) + row * NBX + bxlo];
        int e = g_prefix[b * (NBINS + 1) + row * NBX + bxhi + 1];
        s_startA[tid] = s; s_cntA[tid] = e - s;
    }
    {   // vectorized w_out -> SMEM (1024 float4 / 128 threads = 8 each)
        const float4* w4 = (const float4*)w_out;
        float4* wo4 = (float4*)wouts;
        #pragma unroll
        for (int r = 0; r < 8; ++r) wo4[tid + r * TPB] = w4[tid + r * TPB];
    }
    if (tid < CH) {
        w2aF[tid] = w2[tid * 3 + 0];
        w2bF[tid] = w2[tid * 3 + 1];
        w2cF[tid] = w2[tid * 3 + 2];
        b2F[tid]  = b2[tid];
        boutF[tid] = b_out[tid];
    }
    if (tid < 9) w1s[tid] = w1[tid];
    if (tid < 3) b1s[tid] = b1[tid];
    __syncthreads();
    if (tid == 0) {
        int off = 0;
        for (int r = 0; r < nrows; ++r) { s_offA[r] = off; off += s_cntA[r]; }
        s_totalA = off;
    }
    __syncthreads();
    const int total = s_totalA;
    const bool ovf = total > CAND_MAX;
    if (!ovf) {
        for (int r = 0; r < nrows; ++r) {      // contiguous coalesced ranges -> SoA
            int c = s_cntA[r], st = s_startA[r], of = s_offA[r];
            for (int i = tid; i < c; i += TPB) {
                float4 p = g_binned[b * NP + st + i];
                candPx[of + i] = p.x; candPy[of + i] = p.y;
                candPsq[of + i] = p.z; candIdx[of + i] = __float_as_int(p.w);
            }
        }
        if (tid < 8) {   // sentinel pad to float4 boundary
            candPx[total + tid] = 0.f; candPy[total + tid] = 0.f;
            candPsq[total + tid] = 1e30f; candIdx[total + tid] = 0x7ffffff0;
        }
    }
    __syncthreads();

    // ---- Phase 1: KNN, 4 candidates/iter via LDS.128 ----
    float d0 = INFINITY, d1 = INFINITY, d2b = INFINITY;
    int   i0 = 0x7fffffff, i1 = 0x7fffffff, i2 = 0x7fffffff;
    int   s0 = 0, s1 = 0, s2 = 0;
    bool  fb = false;
    if (!ovf) {
        const float4* px4  = (const float4*)candPx;
        const float4* py4  = (const float4*)candPy;
        const float4* psq4 = (const float4*)candPsq;
        const ull gx2 = pk2(gx, gx), gy2 = pk2(gy, gy), qsq2 = pk2(qsq, qsq);
        int nq = (total + 3) >> 2;
        #pragma unroll 2
        for (int jq = 0; jq < nq; ++jq) {
            float4 PX = px4[jq], PY = py4[jq], PSQ = psq4[jq];
            ull crA = fma2_(pk2(PY.x, PY.y), gy2, mul2_(pk2(PX.x, PX.y), gx2));
            ull ddA = sub2_(add2_(qsq2, pk2(PSQ.x, PSQ.y)), add2_(crA, crA));
            ull crB = fma2_(pk2(PY.z, PY.w), gy2, mul2_(pk2(PX.z, PX.w), gx2));
            ull ddB = sub2_(add2_(qsq2, pk2(PSQ.z, PSQ.w)), add2_(crB, crB));
            float a0, a1, a2, a3;
            upk2(a0, a1, ddA); upk2(a2, a3, ddB);
            int base = 4 * jq;
            if (a0 <= d2b) { int pi = candIdx[base + 0]; INSERT(a0, pi, base + 0); }
            if (a1 <= d2b) { int pi = candIdx[base + 1]; INSERT(a1, pi, base + 1); }
            if (a2 <= d2b) { int pi = candIdx[base + 2]; INSERT(a2, pi, base + 2); }
            if (a3 <= d2b) { int pi = candIdx[base + 3]; INSERT(a3, pi, base + 3); }
        }
    }
    // completeness: any excluded point is >= dmin away
    float dl = (bxlo > 0)       ? (gx - (float)(bxlo * BSZ))       : 1e9f;
    float dr = (bxhi < NBX - 1) ? ((float)((bxhi + 1) * BSZ) - gx) : 1e9f;
    float dt = (bylo > 0)       ? (gy - (float)(bylo * BSZ))       : 1e9f;
    float db = (byhi < NBY - 1) ? ((float)((byhi + 1) * BSZ) - gy) : 1e9f;
    float dmin = fminf(fminf(dl, dr), fminf(dt, db));
    if (ovf || !(d2b + 0.25f <= dmin * dmin)) {    // rare exact fallback
        fb = true;
        d0 = d1 = d2b = INFINITY; i0 = i1 = i2 = 0x7fffffff;
        const float4* gp = g_binned + b * NP;
        #pragma unroll 4
        for (int j = 0; j < NP; ++j) {
            float4 p = gp[j];
            float cr = __fmaf_rn(p.y, gy, __fmul_rn(p.x, gx));
            float dd = __fsub_rn(__fadd_rn(qsq, p.z), __fadd_rn(cr, cr));
            if (dd <= d2b) { int pi = __float_as_int(p.w); INSERT(dd, pi, j); }
        }
    }

    // ---- Phase 2: score MLP + gather ----
    ull fin2[CH / 2];
    #pragma unroll
    for (int c = 0; c < CH / 2; ++c) fin2[c] = 0ull;

    const ull HALF2 = 0x3F0000003F000000ULL;
    const ull* w2a2 = (const ull*)w2aF;
    const ull* w2b2 = (const ull*)w2bF;
    const ull* w2c2 = (const ull*)w2cF;
    const ull* b2p2 = (const ull*)b2F;

    int nidx[3] = { i0, i1, i2 };
    int nsl[3]  = { s0, s1, s2 };
    ull hp0[3], hp1[3], hp2[3];
    #pragma unroll
    for (int k = 0; k < 3; ++k) {
        float px, py;
        if (!fb) { px = candPx[nsl[k]]; py = candPy[nsl[k]]; }
        else     { float4 p = g_binned[b * NP + nsl[k]]; px = p.x; py = p.y; }
        float dx = __fsub_rn(px, gx);
        float dy = __fsub_rn(py, gy);
        float nrm = __fsqrt_rn(__fadd_rn(__fmul_rn(dx, dx), __fmul_rn(dy, dy)));
        float h[3];
        #pragma unroll
        for (int j = 0; j < 3; ++j) {
            float t = __fmaf_rn(w1s[j*3+2], nrm,
                      __fmaf_rn(w1s[j*3+1], dy, __fmul_rn(w1s[j*3+0], dx)));
            t = t + b1s[j];
            h[j] = (t >= 0.f) ? t : 0.1f * t;
        }
        hp0[k] = pk2(h[0], h[0]); hp1[k] = pk2(h[1], h[1]); hp2[k] = pk2(h[2], h[2]);
    }

    const ulonglong2* fr0 = (const ulonglong2*)(g_featT + ((size_t)(b * NP + nidx[0]) << 6));
    const ulonglong2* fr1 = (const ulonglong2*)(g_featT + ((size_t)(b * NP + nidx[1]) << 6));
    const ulonglong2* fr2 = (const ulonglong2*)(g_featT + ((size_t)(b * NP + nidx[2]) << 6));

    #pragma unroll 4
    for (int c8 = 0; c8 < 16; ++c8) {
        int c2 = 2 * c8;
        ull wa0 = w2a2[c2],   wb0 = w2b2[c2],   wc0 = w2c2[c2],   bb0 = b2p2[c2];
        ull wa1 = w2a2[c2+1], wb1 = w2b2[c2+1], wc1 = w2c2[c2+1], bb1 = b2p2[c2+1];
        ulonglong2 fA = fr0[c8], fB = fr1[c8], fC = fr2[c8];
        #pragma unroll
        for (int k = 0; k < 3; ++k) {
            ulonglong2 f = (k == 0) ? fA : (k == 1) ? fB : fC;
            ull z0 = fma2_(wc0, hp2[k], fma2_(wb0, hp1[k], fma2_(wa0, hp0[k], bb0)));
            ull z1 = fma2_(wc1, hp2[k], fma2_(wb1, hp1[k], fma2_(wa1, hp0[k], bb1)));
            z0 = mul2_(z0, HALF2); z1 = mul2_(z1, HALF2);
            float za, zb, zc, zd;
            upk2(za, zb, z0); upk2(zc, zd, z1);
            float sa = __fmaf_rn(0.5f, tanh_ap(za), 0.5f);
            float sb = __fmaf_rn(0.5f, tanh_ap(zb), 0.5f);
            float sc = __fmaf_rn(0.5f, tanh_ap(zc), 0.5f);
            float sd = __fmaf_rn(0.5f, tanh_ap(zd), 0.5f);
            fin2[c2]     = fma2_(pk2(sa, sb), f.x, fin2[c2]);
            fin2[c2 + 1] = fma2_(pk2(sc, sd), f.y, fin2[c2 + 1]);
        }
    }

    // ---- Phase 3: 64x64 out-conv, lean single-co rows, FFMA2 ----
    float* outb = out + ((size_t)b * CH) * QPB + q;
    #pragma unroll 2
    for (int co = 0; co < CH; ++co) {
        const ulonglong2* wr = (const ulonglong2*)(wouts + co * CH);
        ull a0 = 0, a1 = 0, a2 = 0, a3 = 0;
        #pragma unroll
        for (int c4 = 0; c4 < 16; c4 += 2) {
            ulonglong2 wA = wr[c4], wB = wr[c4 + 1];
            a0 = fma2_(wA.x, fin2[2*c4 + 0], a0);
            a1 = fma2_(wA.y, fin2[2*c4 + 1], a1);
            a2 = fma2_(wB.x, fin2[2*c4 + 2], a2);
            a3 = fma2_(wB.y, fin2[2*c4 + 3], a3);
        }
        ull sA = add2_(add2_(a0, a1), add2_(a2, a3));
        float lo, hi;
        upk2(lo, hi, sA);
        float acc = (lo + hi) + boutF[co];
        acc = (acc >= 0.f) ? acc : 0.1f * acc;
        outb[(size_t)co * QPB] = acc;
    }
}

extern "C" void kernel_launch(void* const* d_in, const int* in_sizes, int n_in,
                              void* d_out, int out_size) {
    const float* uv    = (const float*)d_in[0];
    const float* feat  = (const float*)d_in[1];
    const float* w1    = (const float*)d_in[4];
    const float* b1    = (const float*)d_in[5];
    const float* w2    = (const float*)d_in[6];
    const float* b2    = (const float*)d_in[7];
    const float* w_out = (const float*)d_in[8];
    const float* b_out = (const float*)d_in[9];
    float* out = (float*)d_out;

    k_prep<<<BS + BS * (NP / 64), 512>>>(uv, feat);

    cudaFuncSetAttribute(k_main, cudaFuncAttributeMaxDynamicSharedMemorySize, SMEM_BYTES);
    dim3 grid(IMW / 32, IMH / 4, BS);
    k_main<<<grid, TPB, SMEM_BYTES>>>(w1, b1, w2, b2, w_out, b_out, out);
}

// round 7
// speedup vs baseline: 3.9602x; 1.0730x over previous
#include <cuda_runtime.h>
#include <math.h>

#define BS   2
#define NP   4096
#define CH   64
#define IMH  128
#define IMW  256
#define QPB  (IMH*IMW)
#define TPB  64
#define BSZ  8
#define NBX  (IMW/BSZ)     // 32
#define NBY  (IMH/BSZ)     // 16
#define NBINS (NBX*NBY)    // 512
#define CAND_MAX 512
#define CPAD (CAND_MAX + 8)

typedef unsigned long long ull;

// Scratch (static device arrays: no allocation).
__device__ float  g_featT[BS * NP * CH];    // [b][point][channel]
__device__ float4 g_binned[BS * NP];        // (px, py, psq, idx-as-float), bin-sorted
__device__ int    g_prefix[BS * (NBINS + 1)];

// ---- packed f32x2 helpers ----
__device__ __forceinline__ ull pk2(float lo, float hi) {
    ull r; asm("mov.b64 %0,{%1,%2};" : "=l"(r) : "f"(lo), "f"(hi)); return r;
}
__device__ __forceinline__ void upk2(float& lo, float& hi, ull v) {
    asm("mov.b64 {%0,%1},%2;" : "=f"(lo), "=f"(hi) : "l"(v));
}
__device__ __forceinline__ ull fma2_(ull a, ull b, ull c) {
    ull d; asm("fma.rn.f32x2 %0,%1,%2,%3;" : "=l"(d) : "l"(a), "l"(b), "l"(c)); return d;
}
__device__ __forceinline__ ull mul2_(ull a, ull b) {
    ull d; asm("mul.rn.f32x2 %0,%1,%2;" : "=l"(d) : "l"(a), "l"(b)); return d;
}
__device__ __forceinline__ ull add2_(ull a, ull b) {
    ull d; asm("add.rn.f32x2 %0,%1,%2;" : "=l"(d) : "l"(a), "l"(b)); return d;
}
__device__ __forceinline__ ull sub2_(ull a, ull b) {
    ull d; asm("sub.rn.f32x2 %0,%1,%2;" : "=l"(d) : "l"(a), "l"(b)); return d;
}
__device__ __forceinline__ float tanh_ap(float x) {
    float y; asm("tanh.approx.f32 %0,%1;" : "=f"(y) : "f"(x)); return y;
}

// ============================================================================
// k_prep: blocks [0,BS) bin points (count/scan/scatter in SMEM);
//         blocks [BS, ...) transpose features in 64x64 SMEM tiles.
// ============================================================================
__global__ __launch_bounds__(512, 1)
void k_prep(const float* __restrict__ uv, const float* __restrict__ feat) {
    __shared__ int s_cnt[NBINS];
    __shared__ int s_pfx[NBINS];
    __shared__ float s_tile[64][65];
    const int t = threadIdx.x;
    const int bid = blockIdx.x;

    if (bid < BS) {
        const int b = bid;
        s_cnt[t] = 0;
        __syncthreads();
        const float* uvb = uv + b * 2 * NP;
        float4 myp[8]; int mybin[8];
        #pragma unroll
        for (int r = 0; r < 8; ++r) {
            int i = t + r * 512;
            float px = uvb[i], py = uvb[NP + i];
            float psq = __fadd_rn(__fmul_rn(px, px), __fmul_rn(py, py)); // ref rounding
            int bx = min(max((int)(px * (1.0f / BSZ)), 0), NBX - 1);
            int by = min(max((int)(py * (1.0f / BSZ)), 0), NBY - 1);
            mybin[r] = by * NBX + bx;
            myp[r] = make_float4(px, py, psq, __int_as_float(i));
            atomicAdd(&s_cnt[mybin[r]], 1);
        }
        __syncthreads();
        int v = s_cnt[t];
        s_pfx[t] = v;
        __syncthreads();
        for (int d = 1; d < NBINS; d <<= 1) {
            int add = (t >= d) ? s_pfx[t - d] : 0;
            __syncthreads();
            s_pfx[t] += add;
            __syncthreads();
        }
        g_prefix[b * (NBINS + 1) + t + 1] = s_pfx[t];
        if (t == 0) g_prefix[b * (NBINS + 1)] = 0;
        s_cnt[t] = s_pfx[t] - v;
        __syncthreads();
        #pragma unroll
        for (int r = 0; r < 8; ++r) {
            int pos = atomicAdd(&s_cnt[mybin[r]], 1);
            g_binned[b * NP + pos] = myp[r];
        }
    } else {
        int tb = bid - BS;
        int b  = tb >> 6;
        int i0 = (tb & 63) * 64;
        int c  = t >> 3, j = t & 7;
        #pragma unroll
        for (int rep = 0; rep < 2; ++rep) {
            int i4 = j + rep * 8;
            float4 v = *(const float4*)(feat + ((size_t)(b * CH + c) * NP + i0 + i4 * 4));
            s_tile[i4 * 4 + 0][c] = v.x;
            s_tile[i4 * 4 + 1][c] = v.y;
            s_tile[i4 * 4 + 2][c] = v.z;
            s_tile[i4 * 4 + 3][c] = v.w;
        }
        __syncthreads();
        int i = t >> 3;
        #pragma unroll
        for (int rep = 0; rep < 2; ++rep) {
            int c4 = j + rep * 8;
            float4 w;
            w.x = s_tile[i][c4 * 4 + 0];
            w.y = s_tile[i][c4 * 4 + 1];
            w.z = s_tile[i][c4 * 4 + 2];
            w.w = s_tile[i][c4 * 4 + 3];
            *(float4*)(g_featT + ((size_t)(b * NP + i0 + i) << 6) + c4 * 4) = w;
        }
    }
}

// lexicographic top-3 insertion (tie: lower original index) + slot tracking
#define INSERT(dd, pi, sl) {                                                   \
    if ((dd) < d2b || ((dd) == d2b && (pi) < i2)) {                            \
        if ((dd) < d1 || ((dd) == d1 && (pi) < i1)) {                          \
            d2b = d1; i2 = i1; s2 = s1;                                        \
            if ((dd) < d0 || ((dd) == d0 && (pi) < i0))                        \
                 { d1 = d0; i1 = i0; s1 = s0; d0 = (dd); i0 = (pi); s0 = (sl); } \
            else { d1 = (dd); i1 = (pi); s1 = (sl); }                          \
        } else { d2b = (dd); i2 = (pi); s2 = (sl); }                           \
    } }

#define SM_PX    0
#define SM_PY    (SM_PX + CPAD)
#define SM_PSQ   (SM_PY + CPAD)
#define SM_IDX   (SM_PSQ + CPAD)
#define SM_WOUT  (SM_IDX + CPAD)
#define SM_W2A   (SM_WOUT + CH*CH)
#define SM_W2B   (SM_W2A + CH)
#define SM_W2C   (SM_W2B + CH)
#define SM_B2    (SM_W2C + CH)
#define SM_BOUT  (SM_B2 + CH)
#define SM_W1    (SM_BOUT + CH)
#define SM_B1    (SM_W1 + 16)
#define SMEM_FLOATS (SM_B1 + 8)
#define SMEM_BYTES  (SMEM_FLOATS * 4)

__global__ __launch_bounds__(TPB, 8)
void k_main(const float* __restrict__ w1, const float* __restrict__ b1,
            const float* __restrict__ w2, const float* __restrict__ b2,
            const float* __restrict__ w_out, const float* __restrict__ b_out,
            float* __restrict__ out)
{
    extern __shared__ float sm[];
    float* candPx  = sm + SM_PX;
    float* candPy  = sm + SM_PY;
    float* candPsq = sm + SM_PSQ;
    int*   candIdx = (int*)(sm + SM_IDX);
    float* wouts   = sm + SM_WOUT;
    float* w2aF = sm + SM_W2A; float* w2bF = sm + SM_W2B; float* w2cF = sm + SM_W2C;
    float* b2F  = sm + SM_B2;  float* boutF = sm + SM_BOUT;
    float* w1s = sm + SM_W1;   float* b1s = sm + SM_B1;
    __shared__ int s_startA[3], s_cntA[3], s_offA[3], s_totalA;

    const int tid = threadIdx.x;
    const int b   = blockIdx.z;
    const int tx  = tid & 7, ty = tid >> 3;         // 8x8 pixel tile = 1x1 bins
    const int gxi = blockIdx.x * 8 + tx;
    const int gyi = blockIdx.y * 8 + ty;
    const int q   = gyi * IMW + gxi;
    const float gx = (float)gxi, gy = (float)gyi;
    const float qsq = gx * gx + gy * gy;            // exact for integer coords

    // candidate ring: 3x3 bins around the tile's bin
    const int tbx0 = blockIdx.x;
    const int tby0 = blockIdx.y;
    const int bxlo = max(tbx0 - 1, 0), bxhi = min(tbx0 + 1, NBX - 1);
    const int bylo = max(tby0 - 1, 0), byhi = min(tby0 + 1, NBY - 1);
    const int nrows = byhi - bylo + 1;

    if (tid < nrows) {
        int row = bylo + tid;
        int s = g_prefix[b * (NBINS + 1) + row * NBX + bxlo];
        int e = g_prefix[b * (NBINS + 1) + row * NBX + bxhi + 1];
        s_startA[tid] = s; s_cntA[tid] = e - s;
    }
    {   // vectorized w_out -> SMEM (1024 float4 / 64 threads = 16 each)
        const float4* w4 = (const float4*)w_out;
        float4* wo4 = (float4*)wouts;
        #pragma unroll
        for (int r = 0; r < 16; ++r) wo4[tid + r * TPB] = w4[tid + r * TPB];
    }
    if (tid < CH) {
        w2aF[tid] = w2[tid * 3 + 0];
        w2bF[tid] = w2[tid * 3 + 1];
        w2cF[tid] = w2[tid * 3 + 2];
        b2F[tid]  = b2[tid];
        boutF[tid] = b_out[tid];
    }
    if (tid < 9) w1s[tid] = w1[tid];
    if (tid < 3) b1s[tid] = b1[tid];
    __syncthreads();
    if (tid == 0) {
        int off = 0;
        for (int r = 0; r < nrows; ++r) { s_offA[r] = off; off += s_cntA[r]; }
        s_totalA = off;
    }
    __syncthreads();
    const int total = s_totalA;
    const bool ovf = total > CAND_MAX;
    if (!ovf) {
        for (int r = 0; r < nrows; ++r) {      // contiguous coalesced ranges -> SoA
            int c = s_cntA[r], st = s_startA[r], of = s_offA[r];
            for (int i = tid; i < c; i += TPB) {
                float4 p = g_binned[b * NP + st + i];
                candPx[of + i] = p.x; candPy[of + i] = p.y;
                candPsq[of + i] = p.z; candIdx[of + i] = __float_as_int(p.w);
            }
        }
        if (tid < 8) {   // sentinel pad to float4 boundary
            candPx[total + tid] = 0.f; candPy[total + tid] = 0.f;
            candPsq[total + tid] = 1e30f; candIdx[total + tid] = 0x7ffffff0;
        }
    }
    __syncthreads();

    // ---- Phase 1: KNN, 4 candidates/iter via LDS.128 ----
    float d0 = INFINITY, d1 = INFINITY, d2b = INFINITY;
    int   i0 = 0x7fffffff, i1 = 0x7fffffff, i2 = 0x7fffffff;
    int   s0 = 0, s1 = 0, s2 = 0;
    bool  fb = false;
    if (!ovf) {
        const float4* px4  = (const float4*)candPx;
        const float4* py4  = (const float4*)candPy;
        const float4* psq4 = (const float4*)candPsq;
        const ull gx2 = pk2(gx, gx), gy2 = pk2(gy, gy), qsq2 = pk2(qsq, qsq);
        int nq = (total + 3) >> 2;
        #pragma unroll 2
        for (int jq = 0; jq < nq; ++jq) {
            float4 PX = px4[jq], PY = py4[jq], PSQ = psq4[jq];
            ull crA = fma2_(pk2(PY.x, PY.y), gy2, mul2_(pk2(PX.x, PX.y), gx2));
            ull ddA = sub2_(add2_(qsq2, pk2(PSQ.x, PSQ.y)), add2_(crA, crA));
            ull crB = fma2_(pk2(PY.z, PY.w), gy2, mul2_(pk2(PX.z, PX.w), gx2));
            ull ddB = sub2_(add2_(qsq2, pk2(PSQ.z, PSQ.w)), add2_(crB, crB));
            float a0, a1, a2, a3;
            upk2(a0, a1, ddA); upk2(a2, a3, ddB);
            int base = 4 * jq;
            if (a0 <= d2b) { int pi = candIdx[base + 0]; INSERT(a0, pi, base + 0); }
            if (a1 <= d2b) { int pi = candIdx[base + 1]; INSERT(a1, pi, base + 1); }
            if (a2 <= d2b) { int pi = candIdx[base + 2]; INSERT(a2, pi, base + 2); }
            if (a3 <= d2b) { int pi = candIdx[base + 3]; INSERT(a3, pi, base + 3); }
        }
    }
    // completeness: any excluded point is >= dmin away
    float dl = (bxlo > 0)       ? (gx - (float)(bxlo * BSZ))       : 1e9f;
    float dr = (bxhi < NBX - 1) ? ((float)((bxhi + 1) * BSZ) - gx) : 1e9f;
    float dt = (bylo > 0)       ? (gy - (float)(bylo * BSZ))       : 1e9f;
    float db = (byhi < NBY - 1) ? ((float)((byhi + 1) * BSZ) - gy) : 1e9f;
    float dmin = fminf(fminf(dl, dr), fminf(dt, db));
    if (ovf || !(d2b + 0.25f <= dmin * dmin)) {    // rare exact fallback
        fb = true;
        d0 = d1 = d2b = INFINITY; i0 = i1 = i2 = 0x7fffffff;
        const float4* gp = g_binned + b * NP;
        #pragma unroll 4
        for (int j = 0; j < NP; ++j) {
            float4 p = gp[j];
            float cr = __fmaf_rn(p.y, gy, __fmul_rn(p.x, gx));
            float dd = __fsub_rn(__fadd_rn(qsq, p.z), __fadd_rn(cr, cr));
            if (dd <= d2b) { int pi = __float_as_int(p.w); INSERT(dd, pi, j); }
        }
    }

    // ---- Phase 2: score MLP + gather ----
    ull fin2[CH / 2];
    #pragma unroll
    for (int c = 0; c < CH / 2; ++c) fin2[c] = 0ull;

    const ull HALF2 = 0x3F0000003F000000ULL;
    const ull* w2a2 = (const ull*)w2aF;
    const ull* w2b2 = (const ull*)w2bF;
    const ull* w2c2 = (const ull*)w2cF;
    const ull* b2p2 = (const ull*)b2F;

    int nidx[3] = { i0, i1, i2 };
    int nsl[3]  = { s0, s1, s2 };
    ull hp0[3], hp1[3], hp2[3];
    #pragma unroll
    for (int k = 0; k < 3; ++k) {
        float px, py;
        if (!fb) { px = candPx[nsl[k]]; py = candPy[nsl[k]]; }
        else     { float4 p = g_binned[b * NP + nsl[k]]; px = p.x; py = p.y; }
        float dx = __fsub_rn(px, gx);
        float dy = __fsub_rn(py, gy);
        float nrm = __fsqrt_rn(__fadd_rn(__fmul_rn(dx, dx), __fmul_rn(dy, dy)));
        float h[3];
        #pragma unroll
        for (int j = 0; j < 3; ++j) {
            float t = __fmaf_rn(w1s[j*3+2], nrm,
                      __fmaf_rn(w1s[j*3+1], dy, __fmul_rn(w1s[j*3+0], dx)));
            t = t + b1s[j];
            h[j] = (t >= 0.f) ? t : 0.1f * t;
        }
        hp0[k] = pk2(h[0], h[0]); hp1[k] = pk2(h[1], h[1]); hp2[k] = pk2(h[2], h[2]);
    }

    const ulonglong2* fr0 = (const ulonglong2*)(g_featT + ((size_t)(b * NP + nidx[0]) << 6));
    const ulonglong2* fr1 = (const ulonglong2*)(g_featT + ((size_t)(b * NP + nidx[1]) << 6));
    const ulonglong2* fr2 = (const ulonglong2*)(g_featT + ((size_t)(b * NP + nidx[2]) << 6));

    #pragma unroll 4
    for (int c8 = 0; c8 < 16; ++c8) {
        int c2 = 2 * c8;
        ull wa0 = w2a2[c2],   wb0 = w2b2[c2],   wc0 = w2c2[c2],   bb0 = b2p2[c2];
        ull wa1 = w2a2[c2+1], wb1 = w2b2[c2+1], wc1 = w2c2[c2+1], bb1 = b2p2[c2+1];
        ulonglong2 fA = fr0[c8], fB = fr1[c8], fC = fr2[c8];
        #pragma unroll
        for (int k = 0; k < 3; ++k) {
            ulonglong2 f = (k == 0) ? fA : (k == 1) ? fB : fC;
            ull z0 = fma2_(wc0, hp2[k], fma2_(wb0, hp1[k], fma2_(wa0, hp0[k], bb0)));
            ull z1 = fma2_(wc1, hp2[k], fma2_(wb1, hp1[k], fma2_(wa1, hp0[k], bb1)));
            z0 = mul2_(z0, HALF2); z1 = mul2_(z1, HALF2);
            float za, zb, zc, zd;
            upk2(za, zb, z0); upk2(zc, zd, z1);
            float sa = __fmaf_rn(0.5f, tanh_ap(za), 0.5f);
            float sb = __fmaf_rn(0.5f, tanh_ap(zb), 0.5f);
            float sc = __fmaf_rn(0.5f, tanh_ap(zc), 0.5f);
            float sd = __fmaf_rn(0.5f, tanh_ap(zd), 0.5f);
            fin2[c2]     = fma2_(pk2(sa, sb), f.x, fin2[c2]);
            fin2[c2 + 1] = fma2_(pk2(sc, sd), f.y, fin2[c2 + 1]);
        }
    }

    // ---- Phase 3: 64x64 out-conv, co-pairs for load ILP, FFMA2 ----
    float* outb = out + ((size_t)b * CH) * QPB + q;
    #pragma unroll 2
    for (int co = 0; co < CH; co += 2) {
        const ulonglong2* wr0 = (const ulonglong2*)(wouts + co * CH);
        const ulonglong2* wr1 = (const ulonglong2*)(wouts + co * CH + CH);
        ull a0 = 0, a1 = 0, c0 = 0, c1 = 0;
        #pragma unroll
        for (int c4 = 0; c4 < 16; c4 += 2) {
            ulonglong2 wA = wr0[c4], wA2 = wr0[c4 + 1];
            ulonglong2 wB = wr1[c4], wB2 = wr1[c4 + 1];
            a0 = fma2_(wA.x,  fin2[2*c4 + 0], a0);
            a1 = fma2_(wA.y,  fin2[2*c4 + 1], a1);
            a0 = fma2_(wA2.x, fin2[2*c4 + 2], a0);
            a1 = fma2_(wA2.y, fin2[2*c4 + 3], a1);
            c0 = fma2_(wB.x,  fin2[2*c4 + 0], c0);
            c1 = fma2_(wB.y,  fin2[2*c4 + 1], c1);
            c0 = fma2_(wB2.x, fin2[2*c4 + 2], c0);
            c1 = fma2_(wB2.y, fin2[2*c4 + 3], c1);
        }
        ull sA = add2_(a0, a1), sB = add2_(c0, c1);
        float lo, hi, lo2, hi2;
        upk2(lo, hi, sA); upk2(lo2, hi2, sB);
        float accA = (lo + hi) + boutF[co];
        float accB = (lo2 + hi2) + boutF[co + 1];
        accA = (accA >= 0.f) ? accA : 0.1f * accA;
        accB = (accB >= 0.f) ? accB : 0.1f * accB;
        outb[(size_t)co * QPB] = accA;
        outb[(size_t)(co + 1) * QPB] = accB;
    }
}

extern "C" void kernel_launch(void* const* d_in, const int* in_sizes, int n_in,
                              void* d_out, int out_size) {
    const float* uv    = (const float*)d_in[0];
    const float* feat  = (const float*)d_in[1];
    const float* w1    = (const float*)d_in[4];
    const float* b1    = (const float*)d_in[5];
    const float* w2    = (const float*)d_in[6];
    const float* b2    = (const float*)d_in[7];
    const float* w_out = (const float*)d_in[8];
    const float* b_out = (const float*)d_in[9];
    float* out = (float*)d_out;

    k_prep<<<BS + BS * (NP / 64), 512>>>(uv, feat);

    cudaFuncSetAttribute(k_main, cudaFuncAttributeMaxDynamicSharedMemorySize, SMEM_BYTES);
    dim3 grid(IMW / 8, IMH / 8, BS);
    k_main<<<grid, TPB, SMEM_BYTES>>>(w1, b1, w2, b2, w_out, b_out, out);
}

// round 8
// speedup vs baseline: 4.3628x; 1.1017x over previous
#include <cuda_runtime.h>
#include <math.h>

#define BS   2
#define NP   4096
#define CH   64
#define IMH  128
#define IMW  256
#define QPB  (IMH*IMW)
#define TPB  128
#define BSZ  8
#define NBX  (IMW/BSZ)     // 32
#define NBY  (IMH/BSZ)     // 16
#define NBINS (NBX*NBY)    // 512
#define CAND_MAX 512
#define CPAD (CAND_MAX + 8)

typedef unsigned long long ull;

// Scratch (static device arrays: no allocation).
__device__ float  g_featT[BS * NP * CH];    // [b][point][channel]
__device__ float  g_woutT[CH * CH];         // [cin][cout]
__device__ float4 g_binned[BS * NP];        // (px, py, psq, idx-as-float), bin-sorted
__device__ int    g_prefix[BS * (NBINS + 1)];

// ---- packed f32x2 helpers ----
__device__ __forceinline__ ull pk2(float lo, float hi) {
    ull r; asm("mov.b64 %0,{%1,%2};" : "=l"(r) : "f"(lo), "f"(hi)); return r;
}
__device__ __forceinline__ void upk2(float& lo, float& hi, ull v) {
    asm("mov.b64 {%0,%1},%2;" : "=f"(lo), "=f"(hi) : "l"(v));
}
__device__ __forceinline__ ull fma2_(ull a, ull b, ull c) {
    ull d; asm("fma.rn.f32x2 %0,%1,%2,%3;" : "=l"(d) : "l"(a), "l"(b), "l"(c)); return d;
}
__device__ __forceinline__ ull mul2_(ull a, ull b) {
    ull d; asm("mul.rn.f32x2 %0,%1,%2;" : "=l"(d) : "l"(a), "l"(b)); return d;
}
__device__ __forceinline__ ull add2_(ull a, ull b) {
    ull d; asm("add.rn.f32x2 %0,%1,%2;" : "=l"(d) : "l"(a), "l"(b)); return d;
}
__device__ __forceinline__ ull sub2_(ull a, ull b) {
    ull d; asm("sub.rn.f32x2 %0,%1,%2;" : "=l"(d) : "l"(a), "l"(b)); return d;
}
__device__ __forceinline__ float tanh_ap(float x) {
    float y; asm("tanh.approx.f32 %0,%1;" : "=f"(y) : "f"(x)); return y;
}

// ============================================================================
// k_prep: blocks [0,BS) bin points; blocks [BS, BS+128) transpose features;
//         last block transposes w_out -> g_woutT.
// ============================================================================
__global__ __launch_bounds__(512, 1)
void k_prep(const float* __restrict__ uv, const float* __restrict__ feat,
            const float* __restrict__ w_out) {
    __shared__ int s_cnt[NBINS];
    __shared__ int s_pfx[NBINS];
    __shared__ float s_tile[64][65];
    const int t = threadIdx.x;
    const int bid = blockIdx.x;

    if (bid < BS) {
        const int b = bid;
        s_cnt[t] = 0;
        __syncthreads();
        const float* uvb = uv + b * 2 * NP;
        float4 myp[8]; int mybin[8];
        #pragma unroll
        for (int r = 0; r < 8; ++r) {
            int i = t + r * 512;
            float px = uvb[i], py = uvb[NP + i];
            float psq = __fadd_rn(__fmul_rn(px, px), __fmul_rn(py, py)); // ref rounding
            int bx = min(max((int)(px * (1.0f / BSZ)), 0), NBX - 1);
            int by = min(max((int)(py * (1.0f / BSZ)), 0), NBY - 1);
            mybin[r] = by * NBX + bx;
            myp[r] = make_float4(px, py, psq, __int_as_float(i));
            atomicAdd(&s_cnt[mybin[r]], 1);
        }
        __syncthreads();
        int v = s_cnt[t];
        s_pfx[t] = v;
        __syncthreads();
        for (int d = 1; d < NBINS; d <<= 1) {
            int add = (t >= d) ? s_pfx[t - d] : 0;
            __syncthreads();
            s_pfx[t] += add;
            __syncthreads();
        }
        g_prefix[b * (NBINS + 1) + t + 1] = s_pfx[t];
        if (t == 0) g_prefix[b * (NBINS + 1)] = 0;
        s_cnt[t] = s_pfx[t] - v;
        __syncthreads();
        #pragma unroll
        for (int r = 0; r < 8; ++r) {
            int pos = atomicAdd(&s_cnt[mybin[r]], 1);
            g_binned[b * NP + pos] = myp[r];
        }
    } else if (bid < BS + BS * 64) {
        int tb = bid - BS;
        int b  = tb >> 6;
        int i0 = (tb & 63) * 64;
        int c  = t >> 3, j = t & 7;
        #pragma unroll
        for (int rep = 0; rep < 2; ++rep) {
            int i4 = j + rep * 8;
            float4 v = *(const float4*)(feat + ((size_t)(b * CH + c) * NP + i0 + i4 * 4));
            s_tile[i4 * 4 + 0][c] = v.x;
            s_tile[i4 * 4 + 1][c] = v.y;
            s_tile[i4 * 4 + 2][c] = v.z;
            s_tile[i4 * 4 + 3][c] = v.w;
        }
        __syncthreads();
        int i = t >> 3;
        #pragma unroll
        for (int rep = 0; rep < 2; ++rep) {
            int c4 = j + rep * 8;
            float4 w;
            w.x = s_tile[i][c4 * 4 + 0];
            w.y = s_tile[i][c4 * 4 + 1];
            w.z = s_tile[i][c4 * 4 + 2];
            w.w = s_tile[i][c4 * 4 + 3];
            *(float4*)(g_featT + ((size_t)(b * NP + i0 + i) << 6) + c4 * 4) = w;
        }
    } else {
        // transpose w_out [co][c] -> g_woutT [c][co]
        int c = t >> 3, j = t & 7;      // c = co row here
        #pragma unroll
        for (int rep = 0; rep < 2; ++rep) {
            int i4 = j + rep * 8;
            float4 v = *(const float4*)(w_out + (size_t)c * CH + i4 * 4);
            s_tile[i4 * 4 + 0][c] = v.x;
            s_tile[i4 * 4 + 1][c] = v.y;
            s_tile[i4 * 4 + 2][c] = v.z;
            s_tile[i4 * 4 + 3][c] = v.w;
        }
        __syncthreads();
        int i = t >> 3;                 // i = cin row of g_woutT
        #pragma unroll
        for (int rep = 0; rep < 2; ++rep) {
            int c4 = j + rep * 8;
            float4 w;
            w.x = s_tile[i][c4 * 4 + 0];
            w.y = s_tile[i][c4 * 4 + 1];
            w.z = s_tile[i][c4 * 4 + 2];
            w.w = s_tile[i][c4 * 4 + 3];
            *(float4*)(g_woutT + (size_t)i * CH + c4 * 4) = w;
        }
    }
}

// lexicographic top-3 insertion (tie: lower original index) + slot tracking
#define INSERT(dd, pi, sl) {                                                   \
    if ((dd) < d2b || ((dd) == d2b && (pi) < i2)) {                            \
        if ((dd) < d1 || ((dd) == d1 && (pi) < i1)) {                          \
            d2b = d1; i2 = i1; s2 = s1;                                        \
            if ((dd) < d0 || ((dd) == d0 && (pi) < i0))                        \
                 { d1 = d0; i1 = i0; s1 = s0; d0 = (dd); i0 = (pi); s0 = (sl); } \
            else { d1 = (dd); i1 = (pi); s1 = (sl); }                          \
        } else { d2b = (dd); i2 = (pi); s2 = (sl); }                           \
    } }

// SMEM layout (floats): woutT[4096] | w2/b2/bout/w1/b1 | union{cand | fin[64][128]}
#define SM_WOUT  0
#define SM_W2A   (SM_WOUT + CH*CH)
#define SM_W2B   (SM_W2A + CH)
#define SM_W2C   (SM_W2B + CH)
#define SM_B2    (SM_W2C + CH)
#define SM_BOUT  (SM_B2 + CH)
#define SM_W1    (SM_BOUT + CH)
#define SM_B1    (SM_W1 + 16)
#define SM_UNION (SM_B1 + 8)           // 4448, 16B-aligned
#define SM_PX    SM_UNION
#define SM_PY    (SM_PX + CPAD)
#define SM_PSQ   (SM_PY + CPAD)
#define SM_IDX   (SM_PSQ + CPAD)
#define SM_FIN   SM_UNION              // overlays cand
#define SMEM_FLOATS (SM_UNION + CH * TPB)
#define SMEM_BYTES  (SMEM_FLOATS * 4)

__global__ __launch_bounds__(TPB, 4)
void k_main(const float* __restrict__ w1, const float* __restrict__ b1,
            const float* __restrict__ w2, const float* __restrict__ b2,
            const float* __restrict__ b_out,
            float* __restrict__ out)
{
    extern __shared__ float sm[];
    float* woutT_s = sm + SM_WOUT;
    float* candPx  = sm + SM_PX;
    float* candPy  = sm + SM_PY;
    float* candPsq = sm + SM_PSQ;
    int*   candIdx = (int*)(sm + SM_IDX);
    float* fin_s   = sm + SM_FIN;
    float* w2aF = sm + SM_W2A; float* w2bF = sm + SM_W2B; float* w2cF = sm + SM_W2C;
    float* b2F  = sm + SM_B2;  float* boutF = sm + SM_BOUT;
    float* w1s = sm + SM_W1;   float* b1s = sm + SM_B1;
    __shared__ int s_startA[3], s_cntA[3], s_offA[3], s_totalA;

    const int tid = threadIdx.x;
    const int b   = blockIdx.z;
    const int tx  = tid & 15, ty = tid >> 4;        // 16x8 pixel tile = 2x1 bins
    const int gxi = blockIdx.x * 16 + tx;
    const int gyi = blockIdx.y * 8 + ty;
    const float gx = (float)gxi, gy = (float)gyi;
    const float qsq = gx * gx + gy * gy;            // exact for integer coords

    // candidate ring: 4x3 bins around the tile's 2x1 bins
    const int tbx0 = blockIdx.x * 2;
    const int tby0 = blockIdx.y;
    const int bxlo = max(tbx0 - 1, 0), bxhi = min(tbx0 + 2, NBX - 1);
    const int bylo = max(tby0 - 1, 0), byhi = min(tby0 + 1, NBY - 1);
    const int nrows = byhi - bylo + 1;

    if (tid < nrows) {
        int row = bylo + tid;
        int s = g_prefix[b * (NBINS + 1) + row * NBX + bxlo];
        int e = g_prefix[b * (NBINS + 1) + row * NBX + bxhi + 1];
        s_startA[tid] = s; s_cntA[tid] = e - s;
    }
    {   // g_woutT (already transposed) -> SMEM, coalesced
        const float4* w4 = (const float4*)g_woutT;
        float4* wo4 = (float4*)woutT_s;
        #pragma unroll
        for (int r = 0; r < 8; ++r) wo4[tid + r * TPB] = w4[tid + r * TPB];
    }
    if (tid < CH) {
        w2aF[tid] = w2[tid * 3 + 0];
        w2bF[tid] = w2[tid * 3 + 1];
        w2cF[tid] = w2[tid * 3 + 2];
        b2F[tid]  = b2[tid];
        boutF[tid] = b_out[tid];
    }
    if (tid < 9) w1s[tid] = w1[tid];
    if (tid < 3) b1s[tid] = b1[tid];
    __syncthreads();
    if (tid == 0) {
        int off = 0;
        for (int r = 0; r < nrows; ++r) { s_offA[r] = off; off += s_cntA[r]; }
        s_totalA = off;
    }
    __syncthreads();
    const int total = s_totalA;
    const bool ovf = total > CAND_MAX;
    if (!ovf) {
        for (int r = 0; r < nrows; ++r) {      // contiguous coalesced ranges -> SoA
            int c = s_cntA[r], st = s_startA[r], of = s_offA[r];
            for (int i = tid; i < c; i += TPB) {
                float4 p = g_binned[b * NP + st + i];
                candPx[of + i] = p.x; candPy[of + i] = p.y;
                candPsq[of + i] = p.z; candIdx[of + i] = __float_as_int(p.w);
            }
        }
        if (tid < 8) {   // sentinel pad to float4 boundary
            candPx[total + tid] = 0.f; candPy[total + tid] = 0.f;
            candPsq[total + tid] = 1e30f; candIdx[total + tid] = 0x7ffffff0;
        }
    }
    __syncthreads();

    // ---- Phase 1: KNN, 4 candidates/iter via LDS.128 ----
    float d0 = INFINITY, d1 = INFINITY, d2b = INFINITY;
    int   i0 = 0x7fffffff, i1 = 0x7fffffff, i2 = 0x7fffffff;
    int   s0 = 0, s1 = 0, s2 = 0;
    bool  fb = false;
    if (!ovf) {
        const float4* px4  = (const float4*)candPx;
        const float4* py4  = (const float4*)candPy;
        const float4* psq4 = (const float4*)candPsq;
        const ull gx2 = pk2(gx, gx), gy2 = pk2(gy, gy), qsq2 = pk2(qsq, qsq);
        int nq = (total + 3) >> 2;
        #pragma unroll 2
        for (int jq = 0; jq < nq; ++jq) {
            float4 PX = px4[jq], PY = py4[jq], PSQ = psq4[jq];
            ull crA = fma2_(pk2(PY.x, PY.y), gy2, mul2_(pk2(PX.x, PX.y), gx2));
            ull ddA = sub2_(add2_(qsq2, pk2(PSQ.x, PSQ.y)), add2_(crA, crA));
            ull crB = fma2_(pk2(PY.z, PY.w), gy2, mul2_(pk2(PX.z, PX.w), gx2));
            ull ddB = sub2_(add2_(qsq2, pk2(PSQ.z, PSQ.w)), add2_(crB, crB));
            float a0, a1, a2, a3;
            upk2(a0, a1, ddA); upk2(a2, a3, ddB);
            int base = 4 * jq;
            if (a0 <= d2b) { int pi = candIdx[base + 0]; INSERT(a0, pi, base + 0); }
            if (a1 <= d2b) { int pi = candIdx[base + 1]; INSERT(a1, pi, base + 1); }
            if (a2 <= d2b) { int pi = candIdx[base + 2]; INSERT(a2, pi, base + 2); }
            if (a3 <= d2b) { int pi = candIdx[base + 3]; INSERT(a3, pi, base + 3); }
        }
    }
    // completeness: any excluded point is >= dmin away
    float dl = (bxlo > 0)       ? (gx - (float)(bxlo * BSZ))       : 1e9f;
    float dr = (bxhi < NBX - 1) ? ((float)((bxhi + 1) * BSZ) - gx) : 1e9f;
    float dt = (bylo > 0)       ? (gy - (float)(bylo * BSZ))       : 1e9f;
    float db = (byhi < NBY - 1) ? ((float)((byhi + 1) * BSZ) - gy) : 1e9f;
    float dmin = fminf(fminf(dl, dr), fminf(dt, db));
    if (ovf || !(d2b + 0.25f <= dmin * dmin)) {    // rare exact fallback
        fb = true;
        d0 = d1 = d2b = INFINITY; i0 = i1 = i2 = 0x7fffffff;
        const float4* gp = g_binned + b * NP;
        #pragma unroll 4
        for (int j = 0; j < NP; ++j) {
            float4 p = gp[j];
            float cr = __fmaf_rn(p.y, gy, __fmul_rn(p.x, gx));
            float dd = __fsub_rn(__fadd_rn(qsq, p.z), __fadd_rn(cr, cr));
            if (dd <= d2b) { int pi = __float_as_int(p.w); INSERT(dd, pi, j); }
        }
    }

    // ---- Phase 2 part A: neighbor geometry -> h (reads cand) ----
    int nidx[3] = { i0, i1, i2 };
    int nsl[3]  = { s0, s1, s2 };
    ull hp0[3], hp1[3], hp2[3];
    #pragma unroll
    for (int k = 0; k < 3; ++k) {
        float px, py;
        if (!fb) { px = candPx[nsl[k]]; py = candPy[nsl[k]]; }
        else     { float4 p = g_binned[b * NP + nsl[k]]; px = p.x; py = p.y; }
        float dx = __fsub_rn(px, gx);
        float dy = __fsub_rn(py, gy);
        float nrm = __fsqrt_rn(__fadd_rn(__fmul_rn(dx, dx), __fmul_rn(dy, dy)));
        float h[3];
        #pragma unroll
        for (int j = 0; j < 3; ++j) {
            float t = __fmaf_rn(w1s[j*3+2], nrm,
                      __fmaf_rn(w1s[j*3+1], dy, __fmul_rn(w1s[j*3+0], dx)));
            t = t + b1s[j];
            h[j] = (t >= 0.f) ? t : 0.1f * t;
        }
        hp0[k] = pk2(h[0], h[0]); hp1[k] = pk2(h[1], h[1]); hp2[k] = pk2(h[2], h[2]);
    }
    __syncthreads();   // all cand reads done; fin_s may now overwrite the union

    // ---- Phase 2 part B: score + gather -> fin_s[c][px] ----
    const ull HALF2 = 0x3F0000003F000000ULL;
    const ull* w2a2 = (const ull*)w2aF;
    const ull* w2b2 = (const ull*)w2bF;
    const ull* w2c2 = (const ull*)w2cF;
    const ull* b2p2 = (const ull*)b2F;
    const ulonglong2* fr0 = (const ulonglong2*)(g_featT + ((size_t)(b * NP + nidx[0]) << 6));
    const ulonglong2* fr1 = (const ulonglong2*)(g_featT + ((size_t)(b * NP + nidx[1]) << 6));
    const ulonglong2* fr2 = (const ulonglong2*)(g_featT + ((size_t)(b * NP + nidx[2]) << 6));

    #pragma unroll 4
    for (int c8 = 0; c8 < 16; ++c8) {
        int c2 = 2 * c8;
        ull wa0 = w2a2[c2],   wb0 = w2b2[c2],   wc0 = w2c2[c2],   bb0 = b2p2[c2];
        ull wa1 = w2a2[c2+1], wb1 = w2b2[c2+1], wc1 = w2c2[c2+1], bb1 = b2p2[c2+1];
        ulonglong2 fA = fr0[c8], fB = fr1[c8], fC = fr2[c8];
        ull u0 = 0ull, u1 = 0ull;
        #pragma unroll
        for (int k = 0; k < 3; ++k) {
            ulonglong2 f = (k == 0) ? fA : (k == 1) ? fB : fC;
            ull z0 = fma2_(wc0, hp2[k], fma2_(wb0, hp1[k], fma2_(wa0, hp0[k], bb0)));
            ull z1 = fma2_(wc1, hp2[k], fma2_(wb1, hp1[k], fma2_(wa1, hp0[k], bb1)));
            z0 = mul2_(z0, HALF2); z1 = mul2_(z1, HALF2);
            float za, zb, zc, zd;
            upk2(za, zb, z0); upk2(zc, zd, z1);
            float sa = __fmaf_rn(0.5f, tanh_ap(za), 0.5f);
            float sb = __fmaf_rn(0.5f, tanh_ap(zb), 0.5f);
            float sc = __fmaf_rn(0.5f, tanh_ap(zc), 0.5f);
            float sd = __fmaf_rn(0.5f, tanh_ap(zd), 0.5f);
            u0 = fma2_(pk2(sa, sb), f.x, u0);
            u1 = fma2_(pk2(sc, sd), f.y, u1);
        }
        float v0, v1, v2, v3;
        upk2(v0, v1, u0); upk2(v2, v3, u1);
        int cb = 4 * c8;
        fin_s[(cb + 0) * TPB + tid] = v0;     // conflict-free: lanes differ in px
        fin_s[(cb + 1) * TPB + tid] = v1;
        fin_s[(cb + 2) * TPB + tid] = v2;
        fin_s[(cb + 3) * TPB + tid] = v3;
    }
    __syncthreads();

    // ---- Phase 3: block GEMM 128px x 64co, each thread 8px x 8co ----
    const int p0 = 8 * (tid & 15);          // pixel block
    const int c0 = 8 * (tid >> 4);          // cout block
    ull acc[8][4];
    #pragma unroll
    for (int p = 0; p < 8; ++p)
        #pragma unroll
        for (int j = 0; j < 4; ++j) acc[p][j] = 0ull;

    #pragma unroll 4
    for (int c = 0; c < CH; ++c) {
        const float4* frp = (const float4*)(fin_s + c * TPB + p0);
        float4 fA = frp[0], fB = frp[1];
        const ulonglong2* wrp = (const ulonglong2*)(woutT_s + c * CH + c0);
        ulonglong2 w01 = wrp[0], w23 = wrp[1];
        ull fp;
        fp = pk2(fA.x, fA.x);
        acc[0][0]=fma2_(w01.x,fp,acc[0][0]); acc[0][1]=fma2_(w01.y,fp,acc[0][1]);
        acc[0][2]=fma2_(w23.x,fp,acc[0][2]); acc[0][3]=fma2_(w23.y,fp,acc[0][3]);
        fp = pk2(fA.y, fA.y);
        acc[1][0]=fma2_(w01.x,fp,acc[1][0]); acc[1][1]=fma2_(w01.y,fp,acc[1][1]);
        acc[1][2]=fma2_(w23.x,fp,acc[1][2]); acc[1][3]=fma2_(w23.y,fp,acc[1][3]);
        fp = pk2(fA.z, fA.z);
        acc[2][0]=fma2_(w01.x,fp,acc[2][0]); acc[2][1]=fma2_(w01.y,fp,acc[2][1]);
        acc[2][2]=fma2_(w23.x,fp,acc[2][2]); acc[2][3]=fma2_(w23.y,fp,acc[2][3]);
        fp = pk2(fA.w, fA.w);
        acc[3][0]=fma2_(w01.x,fp,acc[3][0]); acc[3][1]=fma2_(w01.y,fp,acc[3][1]);
        acc[3][2]=fma2_(w23.x,fp,acc[3][2]); acc[3][3]=fma2_(w23.y,fp,acc[3][3]);
        fp = pk2(fB.x, fB.x);
        acc[4][0]=fma2_(w01.x,fp,acc[4][0]); acc[4][1]=fma2_(w01.y,fp,acc[4][1]);
        acc[4][2]=fma2_(w23.x,fp,acc[4][2]); acc[4][3]=fma2_(w23.y,fp,acc[4][3]);
        fp = pk2(fB.y, fB.y);
        acc[5][0]=fma2_(w01.x,fp,acc[5][0]); acc[5][1]=fma2_(w01.y,fp,acc[5][1]);
        acc[5][2]=fma2_(w23.x,fp,acc[5][2]); acc[5][3]=fma2_(w23.y,fp,acc[5][3]);
        fp = pk2(fB.z, fB.z);
        acc[6][0]=fma2_(w01.x,fp,acc[6][0]); acc[6][1]=fma2_(w01.y,fp,acc[6][1]);
        acc[6][2]=fma2_(w23.x,fp,acc[6][2]); acc[6][3]=fma2_(w23.y,fp,acc[6][3]);
        fp = pk2(fB.w, fB.w);
        acc[7][0]=fma2_(w01.x,fp,acc[7][0]); acc[7][1]=fma2_(w01.y,fp,acc[7][1]);
        acc[7][2]=fma2_(w23.x,fp,acc[7][2]); acc[7][3]=fma2_(w23.y,fp,acc[7][3]);
    }

    // epilogue: bias + leaky, 8 contiguous px per co -> 2x STG.128
    {
        const int m   = tid & 15;
        const int row = m >> 1, colb = (m & 1) * 8;
        const int q0  = (blockIdx.y * 8 + row) * IMW + blockIdx.x * 16 + colb;
        float* outb = out + ((size_t)b * CH) * QPB + q0;
        #pragma unroll
        for (int j = 0; j < 4; ++j) {
            float lo[8], hi[8];
            #pragma unroll
            for (int p = 0; p < 8; ++p) upk2(lo[p], hi[p], acc[p][j]);
            int coA = c0 + 2 * j, coB = coA + 1;
            float bA = boutF[coA], bB = boutF[coB];
            #pragma unroll
            for (int p = 0; p < 8; ++p) {
                lo[p] += bA; lo[p] = (lo[p] >= 0.f) ? lo[p] : 0.1f * lo[p];
                hi[p] += bB; hi[p] = (hi[p] >= 0.f) ? hi[p] : 0.1f * hi[p];
            }
            float* oA = outb + (size_t)coA * QPB;
            float* oB = outb + (size_t)coB * QPB;
            *(float4*)(oA)     = make_float4(lo[0], lo[1], lo[2], lo[3]);
            *(float4*)(oA + 4) = make_float4(lo[4], lo[5], lo[6], lo[7]);
            *(float4*)(oB)     = make_float4(hi[0], hi[1], hi[2], hi[3]);
            *(float4*)(oB + 4) = make_float4(hi[4], hi[5], hi[6], hi[7]);
        }
    }
}

extern "C" void kernel_launch(void* const* d_in, const int* in_sizes, int n_in,
                              void* d_out, int out_size) {
    const float* uv    = (const float*)d_in[0];
    const float* feat  = (const float*)d_in[1];
    const float* w1    = (const float*)d_in[4];
    const float* b1    = (const float*)d_in[5];
    const float* w2    = (const float*)d_in[6];
    const float* b2    = (const float*)d_in[7];
    const float* w_out = (const float*)d_in[8];
    const float* b_out = (const float*)d_in[9];
    float* out = (float*)d_out;

    k_prep<<<BS + BS * 64 + 1, 512>>>(uv, feat, w_out);

    cudaFuncSetAttribute(k_main, cudaFuncAttributeMaxDynamicSharedMemorySize, SMEM_BYTES);
    dim3 grid(IMW / 16, IMH / 8, BS);
    k_main<<<grid, TPB, SMEM_BYTES>>>(w1, b1, w2, b2, b_out, out);
}